// round 14
// baseline (speedup 1.0000x reference)
#include <cuda_runtime.h>
#include <cuda_bf16.h>
#include <cuda_fp16.h>
#include <stdint.h>
#include <math.h>

#define MAX_N 50000
#define MAX_E 800000
#define DHID 256
#define DIN 512
#define NB_SCAN 128
#define CHUNK0 25088   // 196*128, first row chunk

// Scratch device globals
__device__ int   g_cnt[MAX_N];
__device__ float g_dinv[MAX_N];
__device__ int   g_rowptr[MAX_N + 1];
__device__ int   g_off[MAX_N];
__device__ int   g_blocksum[NB_SCAN];
__device__ int   g_blockoff[NB_SCAN];
__device__ int   g_esrc[MAX_E];
__device__ float g_ecoef[MAX_E];

__device__ __nv_bfloat16 g_xh[(size_t)MAX_N * DIN];
__device__ __nv_bfloat16 g_xl[(size_t)MAX_N * DIN];
__device__ __nv_bfloat16 g_w1h[DIN * DHID];
__device__ __nv_bfloat16 g_w1l[DIN * DHID];
__device__ __nv_bfloat16 g_w2h[DHID * DHID];
__device__ __nv_bfloat16 g_w2l[DHID * DHID];
__device__ __half g_h1[(size_t)MAX_N * DHID];
__device__ __nv_bfloat16 g_a1h[(size_t)MAX_N * DHID];
__device__ __nv_bfloat16 g_a1l[(size_t)MAX_N * DHID];
__device__ __half g_h2[(size_t)MAX_N * DHID];
__device__ __half g_agg2[(size_t)MAX_N * DHID];

// ---------------------------------------------------------------------------
// CSR build
// ---------------------------------------------------------------------------
__global__ void zero_cnt_kernel(int* cnt, int n) {
    int i = blockIdx.x * blockDim.x + threadIdx.x;
    if (i < n) cnt[i] = 0;
}

__global__ void hist_kernel(int* cnt, const int* __restrict__ dst, int e) {
    int i = blockIdx.x * blockDim.x + threadIdx.x;
    if (i < e) atomicAdd(&cnt[dst[i]], 1);
}

__global__ void dinv_kernel(const int* __restrict__ cnt, float* __restrict__ dinv, int n) {
    int i = blockIdx.x * blockDim.x + threadIdx.x;
    if (i < n) dinv[i] = rsqrtf((float)(cnt[i] + 1));
}

__global__ __launch_bounds__(256)
void scan_p1_kernel(const int* __restrict__ cnt, int* __restrict__ blocksum, int n) {
    __shared__ int red[256];
    const int chunk = (n + NB_SCAN - 1) / NB_SCAN;
    const int beg = blockIdx.x * chunk;
    const int end = min(beg + chunk, n);
    int s = 0;
    for (int i = beg + threadIdx.x; i < end; i += 256) s += cnt[i];
    red[threadIdx.x] = s;
    __syncthreads();
    for (int d = 128; d > 0; d >>= 1) {
        if (threadIdx.x < d) red[threadIdx.x] += red[threadIdx.x + d];
        __syncthreads();
    }
    if (threadIdx.x == 0) blocksum[blockIdx.x] = red[0];
}

__global__ __launch_bounds__(NB_SCAN)
void scan_p2_kernel(const int* __restrict__ blocksum, int* __restrict__ blockoff,
                    int* __restrict__ rowptr, int n) {
    __shared__ int sh[NB_SCAN];
    const int t = threadIdx.x;
    sh[t] = blocksum[t];
    __syncthreads();
    for (int d = 1; d < NB_SCAN; d <<= 1) {
        int v = (t >= d) ? sh[t - d] : 0;
        __syncthreads();
        sh[t] += v;
        __syncthreads();
    }
    blockoff[t] = (t == 0) ? 0 : sh[t - 1];
    if (t == NB_SCAN - 1) rowptr[n] = sh[NB_SCAN - 1];
}

__global__ __launch_bounds__(256)
void scan_p3_kernel(const int* __restrict__ cnt, const int* __restrict__ blockoff,
                    int* __restrict__ rowptr, int* __restrict__ off, int n) {
    __shared__ int sh[256];
    const int chunk = (n + NB_SCAN - 1) / NB_SCAN;
    const int beg = blockIdx.x * chunk;
    const int end = min(beg + chunk, n);
    int running = blockoff[blockIdx.x];
    for (int base = beg; base < end; base += 256) {
        const int i = base + threadIdx.x;
        int v = (i < end) ? cnt[i] : 0;
        sh[threadIdx.x] = v;
        __syncthreads();
        for (int d = 1; d < 256; d <<= 1) {
            int t2 = (threadIdx.x >= d) ? sh[threadIdx.x - d] : 0;
            __syncthreads();
            sh[threadIdx.x] += t2;
            __syncthreads();
        }
        if (i < end) {
            const int excl = sh[threadIdx.x] - v;
            rowptr[i] = running + excl;
            off[i] = running + excl;
        }
        running += sh[255];
        __syncthreads();
    }
}

__global__ void scatter_kernel(const int* __restrict__ src, const int* __restrict__ dst,
                               const float* __restrict__ dinv, int* __restrict__ off,
                               int* __restrict__ esrc, float* __restrict__ ecoef, int e) {
    int i = blockIdx.x * blockDim.x + threadIdx.x;
    if (i < e) {
        const int s = src[i];
        const int d = dst[i];
        const int pos = atomicAdd(&off[d], 1);
        esrc[pos] = s;
        ecoef[pos] = dinv[s] * dinv[d];
    }
}

// ---------------------------------------------------------------------------
// fp32 -> (hi, lo) bf16 split
// ---------------------------------------------------------------------------
__global__ void split_kernel(const float* __restrict__ in,
                             __nv_bfloat16* __restrict__ hi,
                             __nv_bfloat16* __restrict__ lo, int n4) {
    int i = blockIdx.x * blockDim.x + threadIdx.x;
    if (i >= n4) return;
    float4 v = reinterpret_cast<const float4*>(in)[i];
    __nv_bfloat16 h0 = __float2bfloat16(v.x);
    __nv_bfloat16 h1 = __float2bfloat16(v.y);
    __nv_bfloat16 h2 = __float2bfloat16(v.z);
    __nv_bfloat16 h3 = __float2bfloat16(v.w);
    hi[i * 4 + 0] = h0; hi[i * 4 + 1] = h1; hi[i * 4 + 2] = h2; hi[i * 4 + 3] = h3;
    lo[i * 4 + 0] = __float2bfloat16(v.x - __bfloat162float(h0));
    lo[i * 4 + 1] = __float2bfloat16(v.y - __bfloat162float(h1));
    lo[i * 4 + 2] = __float2bfloat16(v.z - __bfloat162float(h2));
    lo[i * 4 + 3] = __float2bfloat16(v.w - __bfloat162float(h3));
}

// ---------------------------------------------------------------------------
// Tensor-core GEMM on pre-split bf16 operands (CTA 128x64, BK=16).
// Epilogue writes fp16.
// ---------------------------------------------------------------------------
#define A_PAD 24
#define B_PAD 72

__device__ __forceinline__ void ldsm_x4(uint32_t addr, uint32_t& r0, uint32_t& r1,
                                        uint32_t& r2, uint32_t& r3) {
    asm volatile("ldmatrix.sync.aligned.m8n8.x4.shared.b16 {%0,%1,%2,%3}, [%4];"
                 : "=r"(r0), "=r"(r1), "=r"(r2), "=r"(r3) : "r"(addr));
}
__device__ __forceinline__ void ldsm_x4_t(uint32_t addr, uint32_t& r0, uint32_t& r1,
                                          uint32_t& r2, uint32_t& r3) {
    asm volatile("ldmatrix.sync.aligned.m8n8.x4.trans.shared.b16 {%0,%1,%2,%3}, [%4];"
                 : "=r"(r0), "=r"(r1), "=r"(r2), "=r"(r3) : "r"(addr));
}
__device__ __forceinline__ void mma_bf16(float* d, const uint32_t* a, const uint32_t* b) {
    asm volatile("mma.sync.aligned.m16n8k16.row.col.f32.bf16.bf16.f32 "
                 "{%0,%1,%2,%3}, {%4,%5,%6,%7}, {%8,%9}, {%0,%1,%2,%3};"
                 : "+f"(d[0]), "+f"(d[1]), "+f"(d[2]), "+f"(d[3])
                 : "r"(a[0]), "r"(a[1]), "r"(a[2]), "r"(a[3]), "r"(b[0]), "r"(b[1]));
}
__device__ __forceinline__ void cp_async16(void* smem_dst, const void* gsrc, bool pred) {
    uint32_t saddr = (uint32_t)__cvta_generic_to_shared(smem_dst);
    int sz = pred ? 16 : 0;
    asm volatile("cp.async.cg.shared.global [%0], [%1], 16, %2;"
                 :: "r"(saddr), "l"(gsrc), "r"(sz));
}

__global__ __launch_bounds__(256)
void mma_gemm_pre_kernel(const __nv_bfloat16* __restrict__ Ahg,
                         const __nv_bfloat16* __restrict__ Alg,
                         const __nv_bfloat16* __restrict__ Bhg,
                         const __nv_bfloat16* __restrict__ Blg,
                         __half* __restrict__ C, int M, int K, int N) {
    __shared__ __nv_bfloat16 Ah[2][128][A_PAD];
    __shared__ __nv_bfloat16 Al[2][128][A_PAD];
    __shared__ __nv_bfloat16 Bh[2][16][B_PAD];
    __shared__ __nv_bfloat16 Bl[2][16][B_PAD];

    const int tid = threadIdx.x;
    const int wid = tid >> 5;
    const int lane = tid & 31;
    const int warp_m = wid & 3;
    const int warp_n = wid >> 2;
    const int rowBase = blockIdx.y * 128;
    const int colBase = blockIdx.x * 64;

    const int a_r = tid >> 1;
    const int a_k = (tid & 1) << 3;
    const int arow = rowBase + a_r;
    const bool a_ok = (arow < M);
    const int bt = tid & 127;
    const int b_r = bt >> 3;
    const int b_c = (bt & 7) << 3;
    const bool is_bh = (tid < 128);

    const int lrow = lane & 7;
    const int lmat = lane >> 3;
    const int a_mloc = ((lmat & 1) << 3) + lrow;
    const int a_khalf = lmat >> 1;
    const int b_krow = ((lmat & 1) << 3) + lrow;
    const int b_nhalf = lmat >> 1;

    float acc[2][4][4];
#pragma unroll
    for (int i = 0; i < 2; i++)
#pragma unroll
        for (int j = 0; j < 4; j++)
#pragma unroll
            for (int q = 0; q < 4; q++) acc[i][j][q] = 0.0f;

    const int KT = K >> 4;

    {
        cp_async16(&Ah[0][a_r][a_k], Ahg + (size_t)arow * K + a_k, a_ok);
        cp_async16(&Al[0][a_r][a_k], Alg + (size_t)arow * K + a_k, a_ok);
        if (is_bh)
            cp_async16(&Bh[0][b_r][b_c], Bhg + (size_t)b_r * N + colBase + b_c, true);
        else
            cp_async16(&Bl[0][b_r][b_c], Blg + (size_t)b_r * N + colBase + b_c, true);
        asm volatile("cp.async.commit_group;");
    }

    int buf = 0;
    for (int kt = 0; kt < KT; kt++) {
        asm volatile("cp.async.wait_group 0;");
        __syncthreads();

        if (kt + 1 < KT) {
            const int k0 = (kt + 1) << 4;
            const int nb = buf ^ 1;
            cp_async16(&Ah[nb][a_r][a_k], Ahg + (size_t)arow * K + k0 + a_k, a_ok);
            cp_async16(&Al[nb][a_r][a_k], Alg + (size_t)arow * K + k0 + a_k, a_ok);
            if (is_bh)
                cp_async16(&Bh[nb][b_r][b_c], Bhg + (size_t)(k0 + b_r) * N + colBase + b_c, true);
            else
                cp_async16(&Bl[nb][b_r][b_c], Blg + (size_t)(k0 + b_r) * N + colBase + b_c, true);
            asm volatile("cp.async.commit_group;");
        }

        uint32_t ah[2][4], al[2][4];
#pragma unroll
        for (int mf = 0; mf < 2; mf++) {
            const int m_base = warp_m * 32 + mf * 16;
            uint32_t addr_h = (uint32_t)__cvta_generic_to_shared(
                &Ah[buf][m_base + a_mloc][a_khalf * 8]);
            ldsm_x4(addr_h, ah[mf][0], ah[mf][1], ah[mf][2], ah[mf][3]);
            uint32_t addr_l = (uint32_t)__cvta_generic_to_shared(
                &Al[buf][m_base + a_mloc][a_khalf * 8]);
            ldsm_x4(addr_l, al[mf][0], al[mf][1], al[mf][2], al[mf][3]);
        }
        uint32_t bh[2][4], bl[2][4];
#pragma unroll
        for (int g = 0; g < 2; g++) {
            const int n_base = warp_n * 32 + g * 16;
            uint32_t addr_h = (uint32_t)__cvta_generic_to_shared(
                &Bh[buf][b_krow][n_base + b_nhalf * 8]);
            ldsm_x4_t(addr_h, bh[g][0], bh[g][1], bh[g][2], bh[g][3]);
            uint32_t addr_l = (uint32_t)__cvta_generic_to_shared(
                &Bl[buf][b_krow][n_base + b_nhalf * 8]);
            ldsm_x4_t(addr_l, bl[g][0], bl[g][1], bl[g][2], bl[g][3]);
        }
#pragma unroll
        for (int mf = 0; mf < 2; mf++) {
#pragma unroll
            for (int g = 0; g < 2; g++) {
#pragma unroll
                for (int h = 0; h < 2; h++) {
                    float* d = acc[mf][g * 2 + h];
                    const uint32_t bhp[2] = {bh[g][h * 2], bh[g][h * 2 + 1]};
                    const uint32_t blp[2] = {bl[g][h * 2], bl[g][h * 2 + 1]};
                    mma_bf16(d, ah[mf], bhp);
                    mma_bf16(d, ah[mf], blp);
                    mma_bf16(d, al[mf], bhp);
                }
            }
        }
        buf ^= 1;
    }

    const int lq = lane >> 2;
    const int lr = lane & 3;
#pragma unroll
    for (int mf = 0; mf < 2; mf++) {
#pragma unroll
        for (int g = 0; g < 2; g++) {
#pragma unroll
            for (int h = 0; h < 2; h++) {
                const float* d = acc[mf][g * 2 + h];
                const int col = colBase + warp_n * 32 + g * 16 + h * 8 + lr * 2;
                const int r0 = rowBase + warp_m * 32 + mf * 16 + lq;
                if (r0 < M)
                    *reinterpret_cast<__half2*>(C + (size_t)r0 * N + col) =
                        __floats2half2_rn(d[0], d[1]);
                const int r1 = r0 + 8;
                if (r1 < M)
                    *reinterpret_cast<__half2*>(C + (size_t)r1 * N + col) =
                        __floats2half2_rn(d[2], d[3]);
            }
        }
    }
}

// ---------------------------------------------------------------------------
// CSR aggregation from fp16 h — 32 threads/node, 8 dims (16B) per thread,
// 4-edge unroll. fp32 accumulate. Node range [nbeg, nend).
// MODE 1: relu + bf16 split write. MODE 2: fp16 write.
// ---------------------------------------------------------------------------
__device__ __forceinline__ void acc8_add(float* acc, const uint4& v, float cc) {
    const __half2* p = reinterpret_cast<const __half2*>(&v);
#pragma unroll
    for (int i = 0; i < 4; i++) {
        float2 f = __half22float2(p[i]);
        acc[2 * i + 0] = fmaf(cc, f.x, acc[2 * i + 0]);
        acc[2 * i + 1] = fmaf(cc, f.y, acc[2 * i + 1]);
    }
}

template <int MODE>
__global__ __launch_bounds__(256)
void agg_csr_kernel(const __half* __restrict__ h, const float* __restrict__ bias,
                    const float* __restrict__ dinv,
                    const int* __restrict__ rowptr, const int* __restrict__ esrc,
                    const float* __restrict__ ecoef,
                    __half* __restrict__ outfp16,
                    __nv_bfloat16* __restrict__ outh,
                    __nv_bfloat16* __restrict__ outl, int nbeg, int nend) {
    const int node = nbeg + blockIdx.x * 8 + (threadIdx.x >> 5);
    if (node >= nend) return;
    const int c = (threadIdx.x & 31) << 3;

    const float di = dinv[node];
    const float ws = di * di;
    float acc[8];
    {
        uint4 hv = *reinterpret_cast<const uint4*>(h + (size_t)node * DHID + c);
        const __half2* hh = reinterpret_cast<const __half2*>(&hv);
        float4 b0 = *reinterpret_cast<const float4*>(bias + c);
        float4 b1 = *reinterpret_cast<const float4*>(bias + c + 4);
        float2 f;
        f = __half22float2(hh[0]); acc[0] = fmaf(f.x, ws, b0.x); acc[1] = fmaf(f.y, ws, b0.y);
        f = __half22float2(hh[1]); acc[2] = fmaf(f.x, ws, b0.z); acc[3] = fmaf(f.y, ws, b0.w);
        f = __half22float2(hh[2]); acc[4] = fmaf(f.x, ws, b1.x); acc[5] = fmaf(f.y, ws, b1.y);
        f = __half22float2(hh[3]); acc[6] = fmaf(f.x, ws, b1.z); acc[7] = fmaf(f.y, ws, b1.w);
    }

    const int beg = rowptr[node];
    const int end = rowptr[node + 1];
    int e = beg;
    for (; e + 4 <= end; e += 4) {
        const int s0 = esrc[e + 0];
        const int s1 = esrc[e + 1];
        const int s2 = esrc[e + 2];
        const int s3 = esrc[e + 3];
        const float c0 = ecoef[e + 0];
        const float c1 = ecoef[e + 1];
        const float c2 = ecoef[e + 2];
        const float c3 = ecoef[e + 3];
        uint4 v0 = *reinterpret_cast<const uint4*>(h + (size_t)s0 * DHID + c);
        uint4 v1 = *reinterpret_cast<const uint4*>(h + (size_t)s1 * DHID + c);
        uint4 v2 = *reinterpret_cast<const uint4*>(h + (size_t)s2 * DHID + c);
        uint4 v3 = *reinterpret_cast<const uint4*>(h + (size_t)s3 * DHID + c);
        acc8_add(acc, v0, c0);
        acc8_add(acc, v1, c1);
        acc8_add(acc, v2, c2);
        acc8_add(acc, v3, c3);
    }
    for (; e < end; e++) {
        const int s0 = esrc[e];
        const float c0 = ecoef[e];
        uint4 v0 = *reinterpret_cast<const uint4*>(h + (size_t)s0 * DHID + c);
        acc8_add(acc, v0, c0);
    }

    if (MODE == 2) {
        uint4 o;
        __half2* op = reinterpret_cast<__half2*>(&o);
        op[0] = __floats2half2_rn(acc[0], acc[1]);
        op[1] = __floats2half2_rn(acc[2], acc[3]);
        op[2] = __floats2half2_rn(acc[4], acc[5]);
        op[3] = __floats2half2_rn(acc[6], acc[7]);
        *reinterpret_cast<uint4*>(outfp16 + (size_t)node * DHID + c) = o;
    } else {
        __nv_bfloat16 hi8[8], lo8[8];
#pragma unroll
        for (int i = 0; i < 8; i++) {
            float v = fmaxf(acc[i], 0.f);
            __nv_bfloat16 hv = __float2bfloat16(v);
            hi8[i] = hv;
            lo8[i] = __float2bfloat16(v - __bfloat162float(hv));
        }
        *reinterpret_cast<uint4*>(outh + (size_t)node * DHID + c) =
            *reinterpret_cast<const uint4*>(hi8);
        *reinterpret_cast<uint4*>(outl + (size_t)node * DHID + c) =
            *reinterpret_cast<const uint4*>(lo8);
    }
}

// ---------------------------------------------------------------------------
// Edge scoring from fp16 features (one warp per edge, fp32 accumulate).
// ---------------------------------------------------------------------------
__global__ __launch_bounds__(256)
void score_fp16_kernel(const __half* __restrict__ h,
                       const int* __restrict__ src,
                       const int* __restrict__ dst,
                       float* __restrict__ out, int e) {
    unsigned gt = blockIdx.x * blockDim.x + threadIdx.x;
    unsigned ed = gt >> 5;
    const int lane = threadIdx.x & 31;
    if (ed >= (unsigned)e) return;
    const int s = src[ed];
    const int d = dst[ed];
    uint4 su = *(reinterpret_cast<const uint4*>(h + (size_t)s * DHID) + lane);
    uint4 du = *(reinterpret_cast<const uint4*>(h + (size_t)d * DHID) + lane);
    const __half2* sv = reinterpret_cast<const __half2*>(&su);
    const __half2* dv = reinterpret_cast<const __half2*>(&du);
    float acc = 0.0f;
#pragma unroll
    for (int i = 0; i < 4; i++) {
        float2 a = __half22float2(sv[i]);
        float2 b = __half22float2(dv[i]);
        acc = fmaf(a.x, b.x, acc);
        acc = fmaf(a.y, b.y, acc);
    }
#pragma unroll
    for (int off = 16; off > 0; off >>= 1)
        acc += __shfl_xor_sync(0xFFFFFFFFu, acc, off);
    if (lane == 0) out[ed] = 1.0f / (1.0f + expf(-acc));
}

// ---------------------------------------------------------------------------
// Host launcher — CSR on side stream; split_x and agg1 chunk-pipelined
// ---------------------------------------------------------------------------
extern "C" void kernel_launch(void* const* d_in, const int* in_sizes, int n_in,
                              void* d_out, int out_size) {
    const float* x  = (const float*)d_in[0];
    const int*   ei = (const int*)d_in[1];
    const float* W1 = (const float*)d_in[2];
    const float* b1 = (const float*)d_in[3];
    const float* W2 = (const float*)d_in[4];
    const float* b2 = (const float*)d_in[5];
    float* out = (float*)d_out;

    const int N = in_sizes[0] / DIN;
    const int E = in_sizes[1] / 2;
    const int* src = ei;
    const int* dst = ei + E;
    const int N0 = (CHUNK0 < N) ? CHUNK0 : N;   // first row chunk (multiple of 128)
    const int N1 = N - N0;

    int *p_cnt, *p_rowptr, *p_off, *p_esrc, *p_bsum, *p_boff;
    float *p_dinv, *p_ecoef;
    __half *p_h1, *p_h2, *p_agg2;
    __nv_bfloat16 *p_xh, *p_xl, *p_w1h, *p_w1l, *p_w2h, *p_w2l, *p_a1h, *p_a1l;
    cudaGetSymbolAddress((void**)&p_cnt,    g_cnt);
    cudaGetSymbolAddress((void**)&p_dinv,   g_dinv);
    cudaGetSymbolAddress((void**)&p_rowptr, g_rowptr);
    cudaGetSymbolAddress((void**)&p_off,    g_off);
    cudaGetSymbolAddress((void**)&p_bsum,   g_blocksum);
    cudaGetSymbolAddress((void**)&p_boff,   g_blockoff);
    cudaGetSymbolAddress((void**)&p_esrc,   g_esrc);
    cudaGetSymbolAddress((void**)&p_ecoef,  g_ecoef);
    cudaGetSymbolAddress((void**)&p_xh,     g_xh);
    cudaGetSymbolAddress((void**)&p_xl,     g_xl);
    cudaGetSymbolAddress((void**)&p_w1h,    g_w1h);
    cudaGetSymbolAddress((void**)&p_w1l,    g_w1l);
    cudaGetSymbolAddress((void**)&p_w2h,    g_w2h);
    cudaGetSymbolAddress((void**)&p_w2l,    g_w2l);
    cudaGetSymbolAddress((void**)&p_h1,     g_h1);
    cudaGetSymbolAddress((void**)&p_a1h,    g_a1h);
    cudaGetSymbolAddress((void**)&p_a1l,    g_a1l);
    cudaGetSymbolAddress((void**)&p_h2,     g_h2);
    cudaGetSymbolAddress((void**)&p_agg2,   g_agg2);

    static cudaStream_t s_side = nullptr, s_side2 = nullptr;
    static cudaEvent_t  s_fork = nullptr, s_join = nullptr;
    static cudaEvent_t  s_x1 = nullptr, s_g1 = nullptr, s_a1 = nullptr;
    if (s_side == nullptr) {
        cudaStreamCreateWithFlags(&s_side, cudaStreamNonBlocking);
        cudaStreamCreateWithFlags(&s_side2, cudaStreamNonBlocking);
        cudaEventCreateWithFlags(&s_fork, cudaEventDisableTiming);
        cudaEventCreateWithFlags(&s_join, cudaEventDisableTiming);
        cudaEventCreateWithFlags(&s_x1, cudaEventDisableTiming);
        cudaEventCreateWithFlags(&s_g1, cudaEventDisableTiming);
        cudaEventCreateWithFlags(&s_a1, cudaEventDisableTiming);
    }

    const int T = 256;

    // ---- fork ----
    cudaEventRecord(s_fork, 0);
    cudaStreamWaitEvent(s_side, s_fork, 0);
    cudaStreamWaitEvent(s_side2, s_fork, 0);

    // side stream: CSR build chain
    zero_cnt_kernel<<<(N + T - 1) / T, T, 0, s_side>>>(p_cnt, N);
    hist_kernel<<<(E + T - 1) / T, T, 0, s_side>>>(p_cnt, dst, E);
    dinv_kernel<<<(N + T - 1) / T, T, 0, s_side>>>(p_cnt, p_dinv, N);
    scan_p1_kernel<<<NB_SCAN, 256, 0, s_side>>>(p_cnt, p_bsum, N);
    scan_p2_kernel<<<1, NB_SCAN, 0, s_side>>>(p_bsum, p_boff, p_rowptr, N);
    scan_p3_kernel<<<NB_SCAN, 256, 0, s_side>>>(p_cnt, p_boff, p_rowptr, p_off, N);
    scatter_kernel<<<(E + T - 1) / T, T, 0, s_side>>>(src, dst, p_dinv, p_off,
                                                      p_esrc, p_ecoef, E);
    cudaEventRecord(s_join, s_side);

    // side stream 2: split x chunk 1
    {
        int c1_4 = N1 * DIN / 4;
        int off4 = N0 * DIN / 4;
        if (c1_4 > 0)
            split_kernel<<<(c1_4 + T - 1) / T, T, 0, s_side2>>>(
                x + (size_t)off4 * 4, p_xh + (size_t)off4 * 4, p_xl + (size_t)off4 * 4, c1_4);
        cudaEventRecord(s_x1, s_side2);
    }

    // main: weight splits + split x chunk 0 + GEMM1 chunk 0
    {
        int w1n4 = DIN * DHID / 4;
        split_kernel<<<(w1n4 + T - 1) / T, T>>>(W1, p_w1h, p_w1l, w1n4);
        int w2n4 = DHID * DHID / 4;
        split_kernel<<<(w2n4 + T - 1) / T, T>>>(W2, p_w2h, p_w2l, w2n4);
        int c0_4 = N0 * DIN / 4;
        split_kernel<<<(c0_4 + T - 1) / T, T>>>(x, p_xh, p_xl, c0_4);
    }
    {
        dim3 grid(DHID / 64, N0 / 128);
        mma_gemm_pre_kernel<<<grid, 256>>>(p_xh, p_xl, p_w1h, p_w1l, p_h1, N0, DIN, DHID);
    }
    // GEMM1 chunk 1 (needs split_x chunk 1)
    cudaStreamWaitEvent(0, s_x1, 0);
    if (N1 > 0) {
        dim3 grid(DHID / 64, (N1 + 127) / 128);
        mma_gemm_pre_kernel<<<grid, 256>>>(p_xh + (size_t)N0 * DIN, p_xl + (size_t)N0 * DIN,
                                           p_w1h, p_w1l, p_h1 + (size_t)N0 * DHID,
                                           N1, DIN, DHID);
    }
    cudaEventRecord(s_g1, 0);

    // ---- join: agg1 needs CSR + full h1. Chunk agg1 to overlap with GEMM2. ----
    cudaStreamWaitEvent(0, s_join, 0);
    agg_csr_kernel<1><<<(N0 + 7) / 8, 256>>>(p_h1, b1, p_dinv, p_rowptr, p_esrc, p_ecoef,
                                             nullptr, p_a1h, p_a1l, 0, N0);
    // agg1 chunk 1 on side stream 2 (needs CSR + h1)
    cudaStreamWaitEvent(s_side2, s_join, 0);
    cudaStreamWaitEvent(s_side2, s_g1, 0);
    if (N1 > 0)
        agg_csr_kernel<1><<<(N1 + 7) / 8, 256, 0, s_side2>>>(
            p_h1, b1, p_dinv, p_rowptr, p_esrc, p_ecoef,
            nullptr, p_a1h, p_a1l, N0, N);
    cudaEventRecord(s_a1, s_side2);

    // GEMM2 chunk 0 (needs a1 rows [0,N0) only) — overlaps agg1 chunk 1
    {
        dim3 grid(DHID / 64, N0 / 128);
        mma_gemm_pre_kernel<<<grid, 256>>>(p_a1h, p_a1l, p_w2h, p_w2l, p_h2, N0, DHID, DHID);
    }
    // GEMM2 chunk 1
    cudaStreamWaitEvent(0, s_a1, 0);
    if (N1 > 0) {
        dim3 grid(DHID / 64, (N1 + 127) / 128);
        mma_gemm_pre_kernel<<<grid, 256>>>(p_a1h + (size_t)N0 * DHID, p_a1l + (size_t)N0 * DHID,
                                           p_w2h, p_w2l, p_h2 + (size_t)N0 * DHID,
                                           N1, DHID, DHID);
    }

    // agg2 (needs full h2) then score
    agg_csr_kernel<2><<<(N + 7) / 8, 256>>>(p_h2, b2, p_dinv, p_rowptr, p_esrc, p_ecoef,
                                            p_agg2, nullptr, nullptr, 0, N);
    score_fp16_kernel<<<((unsigned)E * 32 + T - 1) / T, T>>>(p_agg2, src, dst, out, E);
}

// round 15
// speedup vs baseline: 1.0550x; 1.0550x over previous
#include <cuda_runtime.h>
#include <cuda_bf16.h>
#include <cuda_fp16.h>
#include <stdint.h>
#include <math.h>

#define MAX_N 50000
#define MAX_E 800000
#define DHID 256
#define DIN 512
#define NB_SCAN 128

// Scratch device globals
__device__ int   g_cnt[MAX_N];
__device__ float g_dinv[MAX_N];
__device__ int   g_rowptr[MAX_N + 1];
__device__ int   g_off[MAX_N];
__device__ int   g_blocksum[NB_SCAN];
__device__ int   g_blockoff[NB_SCAN];
__device__ int   g_esrc[MAX_E];
__device__ float g_ecoef[MAX_E];

__device__ __nv_bfloat16 g_xh[(size_t)MAX_N * DIN];
__device__ __nv_bfloat16 g_xl[(size_t)MAX_N * DIN];
__device__ __nv_bfloat16 g_w1h[DIN * DHID];
__device__ __nv_bfloat16 g_w1l[DIN * DHID];
__device__ __nv_bfloat16 g_w2h[DHID * DHID];
__device__ __nv_bfloat16 g_w2l[DHID * DHID];
__device__ __half g_h1[(size_t)MAX_N * DHID];
__device__ __nv_bfloat16 g_a1h[(size_t)MAX_N * DHID];
__device__ __nv_bfloat16 g_a1l[(size_t)MAX_N * DHID];
__device__ __half g_h2[(size_t)MAX_N * DHID];
__device__ __half g_agg2[(size_t)MAX_N * DHID];

// ---------------------------------------------------------------------------
// CSR build
// ---------------------------------------------------------------------------
__global__ void zero_cnt_kernel(int* cnt, int n) {
    int i = blockIdx.x * blockDim.x + threadIdx.x;
    if (i < n) cnt[i] = 0;
}

__global__ void hist_kernel(int* cnt, const int* __restrict__ dst, int e) {
    int i = blockIdx.x * blockDim.x + threadIdx.x;
    if (i < e) atomicAdd(&cnt[dst[i]], 1);
}

__global__ void dinv_kernel(const int* __restrict__ cnt, float* __restrict__ dinv, int n) {
    int i = blockIdx.x * blockDim.x + threadIdx.x;
    if (i < n) dinv[i] = rsqrtf((float)(cnt[i] + 1));
}

__global__ __launch_bounds__(256)
void scan_p1_kernel(const int* __restrict__ cnt, int* __restrict__ blocksum, int n) {
    __shared__ int red[256];
    const int chunk = (n + NB_SCAN - 1) / NB_SCAN;
    const int beg = blockIdx.x * chunk;
    const int end = min(beg + chunk, n);
    int s = 0;
    for (int i = beg + threadIdx.x; i < end; i += 256) s += cnt[i];
    red[threadIdx.x] = s;
    __syncthreads();
    for (int d = 128; d > 0; d >>= 1) {
        if (threadIdx.x < d) red[threadIdx.x] += red[threadIdx.x + d];
        __syncthreads();
    }
    if (threadIdx.x == 0) blocksum[blockIdx.x] = red[0];
}

__global__ __launch_bounds__(NB_SCAN)
void scan_p2_kernel(const int* __restrict__ blocksum, int* __restrict__ blockoff,
                    int* __restrict__ rowptr, int n) {
    __shared__ int sh[NB_SCAN];
    const int t = threadIdx.x;
    sh[t] = blocksum[t];
    __syncthreads();
    for (int d = 1; d < NB_SCAN; d <<= 1) {
        int v = (t >= d) ? sh[t - d] : 0;
        __syncthreads();
        sh[t] += v;
        __syncthreads();
    }
    blockoff[t] = (t == 0) ? 0 : sh[t - 1];
    if (t == NB_SCAN - 1) rowptr[n] = sh[NB_SCAN - 1];
}

__global__ __launch_bounds__(256)
void scan_p3_kernel(const int* __restrict__ cnt, const int* __restrict__ blockoff,
                    int* __restrict__ rowptr, int* __restrict__ off, int n) {
    __shared__ int sh[256];
    const int chunk = (n + NB_SCAN - 1) / NB_SCAN;
    const int beg = blockIdx.x * chunk;
    const int end = min(beg + chunk, n);
    int running = blockoff[blockIdx.x];
    for (int base = beg; base < end; base += 256) {
        const int i = base + threadIdx.x;
        int v = (i < end) ? cnt[i] : 0;
        sh[threadIdx.x] = v;
        __syncthreads();
        for (int d = 1; d < 256; d <<= 1) {
            int t2 = (threadIdx.x >= d) ? sh[threadIdx.x - d] : 0;
            __syncthreads();
            sh[threadIdx.x] += t2;
            __syncthreads();
        }
        if (i < end) {
            const int excl = sh[threadIdx.x] - v;
            rowptr[i] = running + excl;
            off[i] = running + excl;
        }
        running += sh[255];
        __syncthreads();
    }
}

__global__ void scatter_kernel(const int* __restrict__ src, const int* __restrict__ dst,
                               const float* __restrict__ dinv, int* __restrict__ off,
                               int* __restrict__ esrc, float* __restrict__ ecoef, int e) {
    int i = blockIdx.x * blockDim.x + threadIdx.x;
    if (i < e) {
        const int s = src[i];
        const int d = dst[i];
        const int pos = atomicAdd(&off[d], 1);
        esrc[pos] = s;
        ecoef[pos] = dinv[s] * dinv[d];
    }
}

// ---------------------------------------------------------------------------
// fp32 -> (hi, lo) bf16 split
// ---------------------------------------------------------------------------
__global__ void split_kernel(const float* __restrict__ in,
                             __nv_bfloat16* __restrict__ hi,
                             __nv_bfloat16* __restrict__ lo, int n4) {
    int i = blockIdx.x * blockDim.x + threadIdx.x;
    if (i >= n4) return;
    float4 v = reinterpret_cast<const float4*>(in)[i];
    __nv_bfloat16 h0 = __float2bfloat16(v.x);
    __nv_bfloat16 h1 = __float2bfloat16(v.y);
    __nv_bfloat16 h2 = __float2bfloat16(v.z);
    __nv_bfloat16 h3 = __float2bfloat16(v.w);
    hi[i * 4 + 0] = h0; hi[i * 4 + 1] = h1; hi[i * 4 + 2] = h2; hi[i * 4 + 3] = h3;
    lo[i * 4 + 0] = __float2bfloat16(v.x - __bfloat162float(h0));
    lo[i * 4 + 1] = __float2bfloat16(v.y - __bfloat162float(h1));
    lo[i * 4 + 2] = __float2bfloat16(v.z - __bfloat162float(h2));
    lo[i * 4 + 3] = __float2bfloat16(v.w - __bfloat162float(h3));
}

// ---------------------------------------------------------------------------
// Tensor-core GEMM on pre-split bf16 operands (CTA 128x64, BK=16).
// Epilogue writes fp16.
// ---------------------------------------------------------------------------
#define A_PAD 24
#define B_PAD 72

__device__ __forceinline__ void ldsm_x4(uint32_t addr, uint32_t& r0, uint32_t& r1,
                                        uint32_t& r2, uint32_t& r3) {
    asm volatile("ldmatrix.sync.aligned.m8n8.x4.shared.b16 {%0,%1,%2,%3}, [%4];"
                 : "=r"(r0), "=r"(r1), "=r"(r2), "=r"(r3) : "r"(addr));
}
__device__ __forceinline__ void ldsm_x4_t(uint32_t addr, uint32_t& r0, uint32_t& r1,
                                          uint32_t& r2, uint32_t& r3) {
    asm volatile("ldmatrix.sync.aligned.m8n8.x4.trans.shared.b16 {%0,%1,%2,%3}, [%4];"
                 : "=r"(r0), "=r"(r1), "=r"(r2), "=r"(r3) : "r"(addr));
}
__device__ __forceinline__ void mma_bf16(float* d, const uint32_t* a, const uint32_t* b) {
    asm volatile("mma.sync.aligned.m16n8k16.row.col.f32.bf16.bf16.f32 "
                 "{%0,%1,%2,%3}, {%4,%5,%6,%7}, {%8,%9}, {%0,%1,%2,%3};"
                 : "+f"(d[0]), "+f"(d[1]), "+f"(d[2]), "+f"(d[3])
                 : "r"(a[0]), "r"(a[1]), "r"(a[2]), "r"(a[3]), "r"(b[0]), "r"(b[1]));
}
__device__ __forceinline__ void cp_async16(void* smem_dst, const void* gsrc, bool pred) {
    uint32_t saddr = (uint32_t)__cvta_generic_to_shared(smem_dst);
    int sz = pred ? 16 : 0;
    asm volatile("cp.async.cg.shared.global [%0], [%1], 16, %2;"
                 :: "r"(saddr), "l"(gsrc), "r"(sz));
}

__global__ __launch_bounds__(256)
void mma_gemm_pre_kernel(const __nv_bfloat16* __restrict__ Ahg,
                         const __nv_bfloat16* __restrict__ Alg,
                         const __nv_bfloat16* __restrict__ Bhg,
                         const __nv_bfloat16* __restrict__ Blg,
                         __half* __restrict__ C, int M, int K, int N) {
    __shared__ __nv_bfloat16 Ah[2][128][A_PAD];
    __shared__ __nv_bfloat16 Al[2][128][A_PAD];
    __shared__ __nv_bfloat16 Bh[2][16][B_PAD];
    __shared__ __nv_bfloat16 Bl[2][16][B_PAD];

    const int tid = threadIdx.x;
    const int wid = tid >> 5;
    const int lane = tid & 31;
    const int warp_m = wid & 3;
    const int warp_n = wid >> 2;
    const int rowBase = blockIdx.y * 128;
    const int colBase = blockIdx.x * 64;

    const int a_r = tid >> 1;
    const int a_k = (tid & 1) << 3;
    const int arow = rowBase + a_r;
    const bool a_ok = (arow < M);
    const int bt = tid & 127;
    const int b_r = bt >> 3;
    const int b_c = (bt & 7) << 3;
    const bool is_bh = (tid < 128);

    const int lrow = lane & 7;
    const int lmat = lane >> 3;
    const int a_mloc = ((lmat & 1) << 3) + lrow;
    const int a_khalf = lmat >> 1;
    const int b_krow = ((lmat & 1) << 3) + lrow;
    const int b_nhalf = lmat >> 1;

    float acc[2][4][4];
#pragma unroll
    for (int i = 0; i < 2; i++)
#pragma unroll
        for (int j = 0; j < 4; j++)
#pragma unroll
            for (int q = 0; q < 4; q++) acc[i][j][q] = 0.0f;

    const int KT = K >> 4;

    {
        cp_async16(&Ah[0][a_r][a_k], Ahg + (size_t)arow * K + a_k, a_ok);
        cp_async16(&Al[0][a_r][a_k], Alg + (size_t)arow * K + a_k, a_ok);
        if (is_bh)
            cp_async16(&Bh[0][b_r][b_c], Bhg + (size_t)b_r * N + colBase + b_c, true);
        else
            cp_async16(&Bl[0][b_r][b_c], Blg + (size_t)b_r * N + colBase + b_c, true);
        asm volatile("cp.async.commit_group;");
    }

    int buf = 0;
    for (int kt = 0; kt < KT; kt++) {
        asm volatile("cp.async.wait_group 0;");
        __syncthreads();

        if (kt + 1 < KT) {
            const int k0 = (kt + 1) << 4;
            const int nb = buf ^ 1;
            cp_async16(&Ah[nb][a_r][a_k], Ahg + (size_t)arow * K + k0 + a_k, a_ok);
            cp_async16(&Al[nb][a_r][a_k], Alg + (size_t)arow * K + k0 + a_k, a_ok);
            if (is_bh)
                cp_async16(&Bh[nb][b_r][b_c], Bhg + (size_t)(k0 + b_r) * N + colBase + b_c, true);
            else
                cp_async16(&Bl[nb][b_r][b_c], Blg + (size_t)(k0 + b_r) * N + colBase + b_c, true);
            asm volatile("cp.async.commit_group;");
        }

        uint32_t ah[2][4], al[2][4];
#pragma unroll
        for (int mf = 0; mf < 2; mf++) {
            const int m_base = warp_m * 32 + mf * 16;
            uint32_t addr_h = (uint32_t)__cvta_generic_to_shared(
                &Ah[buf][m_base + a_mloc][a_khalf * 8]);
            ldsm_x4(addr_h, ah[mf][0], ah[mf][1], ah[mf][2], ah[mf][3]);
            uint32_t addr_l = (uint32_t)__cvta_generic_to_shared(
                &Al[buf][m_base + a_mloc][a_khalf * 8]);
            ldsm_x4(addr_l, al[mf][0], al[mf][1], al[mf][2], al[mf][3]);
        }
        uint32_t bh[2][4], bl[2][4];
#pragma unroll
        for (int g = 0; g < 2; g++) {
            const int n_base = warp_n * 32 + g * 16;
            uint32_t addr_h = (uint32_t)__cvta_generic_to_shared(
                &Bh[buf][b_krow][n_base + b_nhalf * 8]);
            ldsm_x4_t(addr_h, bh[g][0], bh[g][1], bh[g][2], bh[g][3]);
            uint32_t addr_l = (uint32_t)__cvta_generic_to_shared(
                &Bl[buf][b_krow][n_base + b_nhalf * 8]);
            ldsm_x4_t(addr_l, bl[g][0], bl[g][1], bl[g][2], bl[g][3]);
        }
#pragma unroll
        for (int mf = 0; mf < 2; mf++) {
#pragma unroll
            for (int g = 0; g < 2; g++) {
#pragma unroll
                for (int h = 0; h < 2; h++) {
                    float* d = acc[mf][g * 2 + h];
                    const uint32_t bhp[2] = {bh[g][h * 2], bh[g][h * 2 + 1]};
                    const uint32_t blp[2] = {bl[g][h * 2], bl[g][h * 2 + 1]};
                    mma_bf16(d, ah[mf], bhp);
                    mma_bf16(d, ah[mf], blp);
                    mma_bf16(d, al[mf], bhp);
                }
            }
        }
        buf ^= 1;
    }

    const int lq = lane >> 2;
    const int lr = lane & 3;
#pragma unroll
    for (int mf = 0; mf < 2; mf++) {
#pragma unroll
        for (int g = 0; g < 2; g++) {
#pragma unroll
            for (int h = 0; h < 2; h++) {
                const float* d = acc[mf][g * 2 + h];
                const int col = colBase + warp_n * 32 + g * 16 + h * 8 + lr * 2;
                const int r0 = rowBase + warp_m * 32 + mf * 16 + lq;
                if (r0 < M)
                    *reinterpret_cast<__half2*>(C + (size_t)r0 * N + col) =
                        __floats2half2_rn(d[0], d[1]);
                const int r1 = r0 + 8;
                if (r1 < M)
                    *reinterpret_cast<__half2*>(C + (size_t)r1 * N + col) =
                        __floats2half2_rn(d[2], d[3]);
            }
        }
    }
}

// ---------------------------------------------------------------------------
// CSR aggregation from fp16 h — 32 threads/node, 8 dims (16B) per thread,
// 4-edge unroll (4x16B gathers in flight). fp32 accumulate.
// MODE 1: relu + bf16 split write. MODE 2: fp16 write.
// ---------------------------------------------------------------------------
__device__ __forceinline__ void acc8_add(float* acc, const uint4& v, float cc) {
    const __half2* p = reinterpret_cast<const __half2*>(&v);
#pragma unroll
    for (int i = 0; i < 4; i++) {
        float2 f = __half22float2(p[i]);
        acc[2 * i + 0] = fmaf(cc, f.x, acc[2 * i + 0]);
        acc[2 * i + 1] = fmaf(cc, f.y, acc[2 * i + 1]);
    }
}

template <int MODE>
__global__ __launch_bounds__(256)
void agg_csr_kernel(const __half* __restrict__ h, const float* __restrict__ bias,
                    const float* __restrict__ dinv,
                    const int* __restrict__ rowptr, const int* __restrict__ esrc,
                    const float* __restrict__ ecoef,
                    __half* __restrict__ outfp16,
                    __nv_bfloat16* __restrict__ outh,
                    __nv_bfloat16* __restrict__ outl, int n) {
    const int node = blockIdx.x * 8 + (threadIdx.x >> 5);
    if (node >= n) return;
    const int c = (threadIdx.x & 31) << 3;   // 8 dims per thread

    const float di = dinv[node];
    const float ws = di * di;
    float acc[8];
    {
        uint4 hv = *reinterpret_cast<const uint4*>(h + (size_t)node * DHID + c);
        const __half2* hh = reinterpret_cast<const __half2*>(&hv);
        float4 b0 = *reinterpret_cast<const float4*>(bias + c);
        float4 b1 = *reinterpret_cast<const float4*>(bias + c + 4);
        float2 f;
        f = __half22float2(hh[0]); acc[0] = fmaf(f.x, ws, b0.x); acc[1] = fmaf(f.y, ws, b0.y);
        f = __half22float2(hh[1]); acc[2] = fmaf(f.x, ws, b0.z); acc[3] = fmaf(f.y, ws, b0.w);
        f = __half22float2(hh[2]); acc[4] = fmaf(f.x, ws, b1.x); acc[5] = fmaf(f.y, ws, b1.y);
        f = __half22float2(hh[3]); acc[6] = fmaf(f.x, ws, b1.z); acc[7] = fmaf(f.y, ws, b1.w);
    }

    const int beg = rowptr[node];
    const int end = rowptr[node + 1];
    int e = beg;
    for (; e + 4 <= end; e += 4) {
        const int s0 = esrc[e + 0];
        const int s1 = esrc[e + 1];
        const int s2 = esrc[e + 2];
        const int s3 = esrc[e + 3];
        const float c0 = ecoef[e + 0];
        const float c1 = ecoef[e + 1];
        const float c2 = ecoef[e + 2];
        const float c3 = ecoef[e + 3];
        uint4 v0 = *reinterpret_cast<const uint4*>(h + (size_t)s0 * DHID + c);
        uint4 v1 = *reinterpret_cast<const uint4*>(h + (size_t)s1 * DHID + c);
        uint4 v2 = *reinterpret_cast<const uint4*>(h + (size_t)s2 * DHID + c);
        uint4 v3 = *reinterpret_cast<const uint4*>(h + (size_t)s3 * DHID + c);
        acc8_add(acc, v0, c0);
        acc8_add(acc, v1, c1);
        acc8_add(acc, v2, c2);
        acc8_add(acc, v3, c3);
    }
    for (; e < end; e++) {
        const int s0 = esrc[e];
        const float c0 = ecoef[e];
        uint4 v0 = *reinterpret_cast<const uint4*>(h + (size_t)s0 * DHID + c);
        acc8_add(acc, v0, c0);
    }

    if (MODE == 2) {
        uint4 o;
        __half2* op = reinterpret_cast<__half2*>(&o);
        op[0] = __floats2half2_rn(acc[0], acc[1]);
        op[1] = __floats2half2_rn(acc[2], acc[3]);
        op[2] = __floats2half2_rn(acc[4], acc[5]);
        op[3] = __floats2half2_rn(acc[6], acc[7]);
        *reinterpret_cast<uint4*>(outfp16 + (size_t)node * DHID + c) = o;
    } else {
        __nv_bfloat16 hi8[8], lo8[8];
#pragma unroll
        for (int i = 0; i < 8; i++) {
            float v = fmaxf(acc[i], 0.f);
            __nv_bfloat16 hv = __float2bfloat16(v);
            hi8[i] = hv;
            lo8[i] = __float2bfloat16(v - __bfloat162float(hv));
        }
        *reinterpret_cast<uint4*>(outh + (size_t)node * DHID + c) =
            *reinterpret_cast<const uint4*>(hi8);
        *reinterpret_cast<uint4*>(outl + (size_t)node * DHID + c) =
            *reinterpret_cast<const uint4*>(lo8);
    }
}

// ---------------------------------------------------------------------------
// Edge scoring from fp16 features (one warp per edge, fp32 accumulate).
// ---------------------------------------------------------------------------
__global__ __launch_bounds__(256)
void score_fp16_kernel(const __half* __restrict__ h,
                       const int* __restrict__ src,
                       const int* __restrict__ dst,
                       float* __restrict__ out, int e) {
    unsigned gt = blockIdx.x * blockDim.x + threadIdx.x;
    unsigned ed = gt >> 5;
    const int lane = threadIdx.x & 31;
    if (ed >= (unsigned)e) return;
    const int s = src[ed];
    const int d = dst[ed];
    uint4 su = *(reinterpret_cast<const uint4*>(h + (size_t)s * DHID) + lane);
    uint4 du = *(reinterpret_cast<const uint4*>(h + (size_t)d * DHID) + lane);
    const __half2* sv = reinterpret_cast<const __half2*>(&su);
    const __half2* dv = reinterpret_cast<const __half2*>(&du);
    float acc = 0.0f;
#pragma unroll
    for (int i = 0; i < 4; i++) {
        float2 a = __half22float2(sv[i]);
        float2 b = __half22float2(dv[i]);
        acc = fmaf(a.x, b.x, acc);
        acc = fmaf(a.y, b.y, acc);
    }
#pragma unroll
    for (int off = 16; off > 0; off >>= 1)
        acc += __shfl_xor_sync(0xFFFFFFFFu, acc, off);
    if (lane == 0) out[ed] = 1.0f / (1.0f + expf(-acc));
}

// ---------------------------------------------------------------------------
// Host launcher — CSR build forked onto a side stream (R13 configuration)
// ---------------------------------------------------------------------------
extern "C" void kernel_launch(void* const* d_in, const int* in_sizes, int n_in,
                              void* d_out, int out_size) {
    const float* x  = (const float*)d_in[0];
    const int*   ei = (const int*)d_in[1];
    const float* W1 = (const float*)d_in[2];
    const float* b1 = (const float*)d_in[3];
    const float* W2 = (const float*)d_in[4];
    const float* b2 = (const float*)d_in[5];
    float* out = (float*)d_out;

    const int N = in_sizes[0] / DIN;
    const int E = in_sizes[1] / 2;
    const int* src = ei;
    const int* dst = ei + E;

    int *p_cnt, *p_rowptr, *p_off, *p_esrc, *p_bsum, *p_boff;
    float *p_dinv, *p_ecoef;
    __half *p_h1, *p_h2, *p_agg2;
    __nv_bfloat16 *p_xh, *p_xl, *p_w1h, *p_w1l, *p_w2h, *p_w2l, *p_a1h, *p_a1l;
    cudaGetSymbolAddress((void**)&p_cnt,    g_cnt);
    cudaGetSymbolAddress((void**)&p_dinv,   g_dinv);
    cudaGetSymbolAddress((void**)&p_rowptr, g_rowptr);
    cudaGetSymbolAddress((void**)&p_off,    g_off);
    cudaGetSymbolAddress((void**)&p_bsum,   g_blocksum);
    cudaGetSymbolAddress((void**)&p_boff,   g_blockoff);
    cudaGetSymbolAddress((void**)&p_esrc,   g_esrc);
    cudaGetSymbolAddress((void**)&p_ecoef,  g_ecoef);
    cudaGetSymbolAddress((void**)&p_xh,     g_xh);
    cudaGetSymbolAddress((void**)&p_xl,     g_xl);
    cudaGetSymbolAddress((void**)&p_w1h,    g_w1h);
    cudaGetSymbolAddress((void**)&p_w1l,    g_w1l);
    cudaGetSymbolAddress((void**)&p_w2h,    g_w2h);
    cudaGetSymbolAddress((void**)&p_w2l,    g_w2l);
    cudaGetSymbolAddress((void**)&p_h1,     g_h1);
    cudaGetSymbolAddress((void**)&p_a1h,    g_a1h);
    cudaGetSymbolAddress((void**)&p_a1l,    g_a1l);
    cudaGetSymbolAddress((void**)&p_h2,     g_h2);
    cudaGetSymbolAddress((void**)&p_agg2,   g_agg2);

    static cudaStream_t s_side = nullptr;
    static cudaEvent_t  s_fork = nullptr, s_join = nullptr;
    if (s_side == nullptr) {
        cudaStreamCreateWithFlags(&s_side, cudaStreamNonBlocking);
        cudaEventCreateWithFlags(&s_fork, cudaEventDisableTiming);
        cudaEventCreateWithFlags(&s_join, cudaEventDisableTiming);
    }

    const int T = 256;

    // ---- fork: CSR build chain on side stream ----
    cudaEventRecord(s_fork, 0);
    cudaStreamWaitEvent(s_side, s_fork, 0);
    zero_cnt_kernel<<<(N + T - 1) / T, T, 0, s_side>>>(p_cnt, N);
    hist_kernel<<<(E + T - 1) / T, T, 0, s_side>>>(p_cnt, dst, E);
    dinv_kernel<<<(N + T - 1) / T, T, 0, s_side>>>(p_cnt, p_dinv, N);
    scan_p1_kernel<<<NB_SCAN, 256, 0, s_side>>>(p_cnt, p_bsum, N);
    scan_p2_kernel<<<1, NB_SCAN, 0, s_side>>>(p_bsum, p_boff, p_rowptr, N);
    scan_p3_kernel<<<NB_SCAN, 256, 0, s_side>>>(p_cnt, p_boff, p_rowptr, p_off, N);
    scatter_kernel<<<(E + T - 1) / T, T, 0, s_side>>>(src, dst, p_dinv, p_off,
                                                      p_esrc, p_ecoef, E);
    cudaEventRecord(s_join, s_side);

    // ---- main stream: splits + GEMM1 ----
    {
        int n4 = N * DIN / 4;
        split_kernel<<<(n4 + T - 1) / T, T>>>(x, p_xh, p_xl, n4);
        int w1n4 = DIN * DHID / 4;
        split_kernel<<<(w1n4 + T - 1) / T, T>>>(W1, p_w1h, p_w1l, w1n4);
        int w2n4 = DHID * DHID / 4;
        split_kernel<<<(w2n4 + T - 1) / T, T>>>(W2, p_w2h, p_w2l, w2n4);
    }
    {
        dim3 grid(DHID / 64, (N + 127) / 128);
        mma_gemm_pre_kernel<<<grid, 256>>>(p_xh, p_xl, p_w1h, p_w1l, p_h1, N, DIN, DHID);
    }

    // ---- join: agg1 needs CSR ----
    cudaStreamWaitEvent(0, s_join, 0);
    agg_csr_kernel<1><<<(N + 7) / 8, 256>>>(p_h1, b1, p_dinv, p_rowptr, p_esrc, p_ecoef,
                                            nullptr, p_a1h, p_a1l, N);

    {
        dim3 grid(DHID / 64, (N + 127) / 128);
        mma_gemm_pre_kernel<<<grid, 256>>>(p_a1h, p_a1l, p_w2h, p_w2l, p_h2, N, DHID, DHID);
    }
    agg_csr_kernel<2><<<(N + 7) / 8, 256>>>(p_h2, b2, p_dinv, p_rowptr, p_esrc, p_ecoef,
                                            p_agg2, nullptr, nullptr, N);

    // ---- edge scoring from fp16 ----
    score_fp16_kernel<<<((unsigned)E * 32 + T - 1) / T, T>>>(p_agg2, src, dst, out, E);
}

// round 16
// speedup vs baseline: 1.3313x; 1.2618x over previous
#include <cuda_runtime.h>
#include <cuda_bf16.h>
#include <cuda_fp16.h>
#include <stdint.h>
#include <math.h>

#define MAX_N 50000
#define MAX_E 800000
#define DHID 256
#define DIN 512
#define NB_SCAN 128

// Scratch device globals
__device__ int   g_cnt[MAX_N];
__device__ float g_dinv[MAX_N];
__device__ int   g_rowptr[MAX_N + 1];
__device__ int   g_off[MAX_N];
__device__ int   g_blocksum[NB_SCAN];
__device__ int   g_blockoff[NB_SCAN];
__device__ int   g_esrc[MAX_E];
__device__ float g_ecoef[MAX_E];

__device__ __half g_xf[(size_t)MAX_N * DIN];     // x rounded to fp16
__device__ __half g_w1h[DIN * DHID];             // W1 fp16 hi
__device__ __half g_w1l[DIN * DHID];             // W1 fp16 lo (residual)
__device__ __half g_w2h[DHID * DHID];
__device__ __half g_w2l[DHID * DHID];
__device__ __half g_h1[(size_t)MAX_N * DHID];
__device__ __half g_a1f[(size_t)MAX_N * DHID];   // relu(agg1) fp16
__device__ __half g_h2[(size_t)MAX_N * DHID];
__device__ __half g_agg2[(size_t)MAX_N * DHID];

// ---------------------------------------------------------------------------
// CSR build
// ---------------------------------------------------------------------------
__global__ void zero_cnt_kernel(int* cnt, int n) {
    int i = blockIdx.x * blockDim.x + threadIdx.x;
    if (i < n) cnt[i] = 0;
}

__global__ void hist_kernel(int* cnt, const int* __restrict__ dst, int e) {
    int i = blockIdx.x * blockDim.x + threadIdx.x;
    if (i < e) atomicAdd(&cnt[dst[i]], 1);
}

__global__ void dinv_kernel(const int* __restrict__ cnt, float* __restrict__ dinv, int n) {
    int i = blockIdx.x * blockDim.x + threadIdx.x;
    if (i < n) dinv[i] = rsqrtf((float)(cnt[i] + 1));
}

__global__ __launch_bounds__(256)
void scan_p1_kernel(const int* __restrict__ cnt, int* __restrict__ blocksum, int n) {
    __shared__ int red[256];
    const int chunk = (n + NB_SCAN - 1) / NB_SCAN;
    const int beg = blockIdx.x * chunk;
    const int end = min(beg + chunk, n);
    int s = 0;
    for (int i = beg + threadIdx.x; i < end; i += 256) s += cnt[i];
    red[threadIdx.x] = s;
    __syncthreads();
    for (int d = 128; d > 0; d >>= 1) {
        if (threadIdx.x < d) red[threadIdx.x] += red[threadIdx.x + d];
        __syncthreads();
    }
    if (threadIdx.x == 0) blocksum[blockIdx.x] = red[0];
}

__global__ __launch_bounds__(NB_SCAN)
void scan_p2_kernel(const int* __restrict__ blocksum, int* __restrict__ blockoff,
                    int* __restrict__ rowptr, int n) {
    __shared__ int sh[NB_SCAN];
    const int t = threadIdx.x;
    sh[t] = blocksum[t];
    __syncthreads();
    for (int d = 1; d < NB_SCAN; d <<= 1) {
        int v = (t >= d) ? sh[t - d] : 0;
        __syncthreads();
        sh[t] += v;
        __syncthreads();
    }
    blockoff[t] = (t == 0) ? 0 : sh[t - 1];
    if (t == NB_SCAN - 1) rowptr[n] = sh[NB_SCAN - 1];
}

__global__ __launch_bounds__(256)
void scan_p3_kernel(const int* __restrict__ cnt, const int* __restrict__ blockoff,
                    int* __restrict__ rowptr, int* __restrict__ off, int n) {
    __shared__ int sh[256];
    const int chunk = (n + NB_SCAN - 1) / NB_SCAN;
    const int beg = blockIdx.x * chunk;
    const int end = min(beg + chunk, n);
    int running = blockoff[blockIdx.x];
    for (int base = beg; base < end; base += 256) {
        const int i = base + threadIdx.x;
        int v = (i < end) ? cnt[i] : 0;
        sh[threadIdx.x] = v;
        __syncthreads();
        for (int d = 1; d < 256; d <<= 1) {
            int t2 = (threadIdx.x >= d) ? sh[threadIdx.x - d] : 0;
            __syncthreads();
            sh[threadIdx.x] += t2;
            __syncthreads();
        }
        if (i < end) {
            const int excl = sh[threadIdx.x] - v;
            rowptr[i] = running + excl;
            off[i] = running + excl;
        }
        running += sh[255];
        __syncthreads();
    }
}

__global__ void scatter_kernel(const int* __restrict__ src, const int* __restrict__ dst,
                               const float* __restrict__ dinv, int* __restrict__ off,
                               int* __restrict__ esrc, float* __restrict__ ecoef, int e) {
    int i = blockIdx.x * blockDim.x + threadIdx.x;
    if (i < e) {
        const int s = src[i];
        const int d = dst[i];
        const int pos = atomicAdd(&off[d], 1);
        esrc[pos] = s;
        ecoef[pos] = dinv[s] * dinv[d];
    }
}

// ---------------------------------------------------------------------------
// fp32 -> fp16 convert (x) and fp32 -> (hi, lo) fp16 split (weights)
// ---------------------------------------------------------------------------
__global__ void cvt16_kernel(const float* __restrict__ in,
                             __half* __restrict__ outp, int n4) {
    int i = blockIdx.x * blockDim.x + threadIdx.x;
    if (i >= n4) return;
    float4 v = reinterpret_cast<const float4*>(in)[i];
    __half2 p0 = __floats2half2_rn(v.x, v.y);
    __half2 p1 = __floats2half2_rn(v.z, v.w);
    *reinterpret_cast<__half2*>(outp + i * 4) = p0;
    *reinterpret_cast<__half2*>(outp + i * 4 + 2) = p1;
}

__global__ void split16_kernel(const float* __restrict__ in,
                               __half* __restrict__ hi,
                               __half* __restrict__ lo, int n4) {
    int i = blockIdx.x * blockDim.x + threadIdx.x;
    if (i >= n4) return;
    float4 v = reinterpret_cast<const float4*>(in)[i];
    __half h0 = __float2half_rn(v.x);
    __half h1 = __float2half_rn(v.y);
    __half h2 = __float2half_rn(v.z);
    __half h3 = __float2half_rn(v.w);
    hi[i * 4 + 0] = h0; hi[i * 4 + 1] = h1; hi[i * 4 + 2] = h2; hi[i * 4 + 3] = h3;
    lo[i * 4 + 0] = __float2half_rn(v.x - __half2float(h0));
    lo[i * 4 + 1] = __float2half_rn(v.y - __half2float(h1));
    lo[i * 4 + 2] = __float2half_rn(v.z - __half2float(h2));
    lo[i * 4 + 3] = __float2half_rn(v.w - __half2float(h3));
}

// ---------------------------------------------------------------------------
// Tensor-core GEMM: C = A_fp16 @ (Bh + Bl), fp32 accumulate, 2 MMAs/step.
// CTA tile 128x64, BK=16, 8 warps (4m x 2n), warp tile 32x32, cp.async 2-stage.
// Epilogue writes fp16.
// ---------------------------------------------------------------------------
#define A_PAD 24
#define B_PAD 72

__device__ __forceinline__ void ldsm_x4(uint32_t addr, uint32_t& r0, uint32_t& r1,
                                        uint32_t& r2, uint32_t& r3) {
    asm volatile("ldmatrix.sync.aligned.m8n8.x4.shared.b16 {%0,%1,%2,%3}, [%4];"
                 : "=r"(r0), "=r"(r1), "=r"(r2), "=r"(r3) : "r"(addr));
}
__device__ __forceinline__ void ldsm_x4_t(uint32_t addr, uint32_t& r0, uint32_t& r1,
                                          uint32_t& r2, uint32_t& r3) {
    asm volatile("ldmatrix.sync.aligned.m8n8.x4.trans.shared.b16 {%0,%1,%2,%3}, [%4];"
                 : "=r"(r0), "=r"(r1), "=r"(r2), "=r"(r3) : "r"(addr));
}
__device__ __forceinline__ void mma_f16(float* d, const uint32_t* a, const uint32_t* b) {
    asm volatile("mma.sync.aligned.m16n8k16.row.col.f32.f16.f16.f32 "
                 "{%0,%1,%2,%3}, {%4,%5,%6,%7}, {%8,%9}, {%0,%1,%2,%3};"
                 : "+f"(d[0]), "+f"(d[1]), "+f"(d[2]), "+f"(d[3])
                 : "r"(a[0]), "r"(a[1]), "r"(a[2]), "r"(a[3]), "r"(b[0]), "r"(b[1]));
}
__device__ __forceinline__ void cp_async16(void* smem_dst, const void* gsrc, bool pred) {
    uint32_t saddr = (uint32_t)__cvta_generic_to_shared(smem_dst);
    int sz = pred ? 16 : 0;
    asm volatile("cp.async.cg.shared.global [%0], [%1], 16, %2;"
                 :: "r"(saddr), "l"(gsrc), "r"(sz));
}

__global__ __launch_bounds__(256)
void mma_gemm_f16_kernel(const __half* __restrict__ Ag,
                         const __half* __restrict__ Bhg,
                         const __half* __restrict__ Blg,
                         __half* __restrict__ C, int M, int K, int N) {
    __shared__ __half Af[2][128][A_PAD];
    __shared__ __half Bh[2][16][B_PAD];
    __shared__ __half Bl[2][16][B_PAD];

    const int tid = threadIdx.x;
    const int wid = tid >> 5;
    const int lane = tid & 31;
    const int warp_m = wid & 3;
    const int warp_n = wid >> 2;
    const int rowBase = blockIdx.y * 128;
    const int colBase = blockIdx.x * 64;

    // A staging: 128 rows x 16 k fp16 = 256 chunks of 8 elems; 1 per thread
    const int a_r = tid >> 1;
    const int a_k = (tid & 1) << 3;
    const int arow = rowBase + a_r;
    const bool a_ok = (arow < M);
    // B staging: 16 rows x 64 cols; tid<128 -> Bh chunk, tid>=128 -> Bl chunk
    const int bt = tid & 127;
    const int b_r = bt >> 3;
    const int b_c = (bt & 7) << 3;
    const bool is_bh = (tid < 128);

    const int lrow = lane & 7;
    const int lmat = lane >> 3;
    const int a_mloc = ((lmat & 1) << 3) + lrow;
    const int a_khalf = lmat >> 1;
    const int b_krow = ((lmat & 1) << 3) + lrow;
    const int b_nhalf = lmat >> 1;

    float acc[2][4][4];
#pragma unroll
    for (int i = 0; i < 2; i++)
#pragma unroll
        for (int j = 0; j < 4; j++)
#pragma unroll
            for (int q = 0; q < 4; q++) acc[i][j][q] = 0.0f;

    const int KT = K >> 4;

    {
        cp_async16(&Af[0][a_r][a_k], Ag + (size_t)arow * K + a_k, a_ok);
        if (is_bh)
            cp_async16(&Bh[0][b_r][b_c], Bhg + (size_t)b_r * N + colBase + b_c, true);
        else
            cp_async16(&Bl[0][b_r][b_c], Blg + (size_t)b_r * N + colBase + b_c, true);
        asm volatile("cp.async.commit_group;");
    }

    int buf = 0;
    for (int kt = 0; kt < KT; kt++) {
        asm volatile("cp.async.wait_group 0;");
        __syncthreads();

        if (kt + 1 < KT) {
            const int k0 = (kt + 1) << 4;
            const int nb = buf ^ 1;
            cp_async16(&Af[nb][a_r][a_k], Ag + (size_t)arow * K + k0 + a_k, a_ok);
            if (is_bh)
                cp_async16(&Bh[nb][b_r][b_c], Bhg + (size_t)(k0 + b_r) * N + colBase + b_c, true);
            else
                cp_async16(&Bl[nb][b_r][b_c], Blg + (size_t)(k0 + b_r) * N + colBase + b_c, true);
            asm volatile("cp.async.commit_group;");
        }

        uint32_t af[2][4];
#pragma unroll
        for (int mf = 0; mf < 2; mf++) {
            const int m_base = warp_m * 32 + mf * 16;
            uint32_t addr = (uint32_t)__cvta_generic_to_shared(
                &Af[buf][m_base + a_mloc][a_khalf * 8]);
            ldsm_x4(addr, af[mf][0], af[mf][1], af[mf][2], af[mf][3]);
        }
        uint32_t bh[2][4], bl[2][4];
#pragma unroll
        for (int g = 0; g < 2; g++) {
            const int n_base = warp_n * 32 + g * 16;
            uint32_t addr_h = (uint32_t)__cvta_generic_to_shared(
                &Bh[buf][b_krow][n_base + b_nhalf * 8]);
            ldsm_x4_t(addr_h, bh[g][0], bh[g][1], bh[g][2], bh[g][3]);
            uint32_t addr_l = (uint32_t)__cvta_generic_to_shared(
                &Bl[buf][b_krow][n_base + b_nhalf * 8]);
            ldsm_x4_t(addr_l, bl[g][0], bl[g][1], bl[g][2], bl[g][3]);
        }
#pragma unroll
        for (int mf = 0; mf < 2; mf++) {
#pragma unroll
            for (int g = 0; g < 2; g++) {
#pragma unroll
                for (int h = 0; h < 2; h++) {
                    float* d = acc[mf][g * 2 + h];
                    const uint32_t bhp[2] = {bh[g][h * 2], bh[g][h * 2 + 1]};
                    const uint32_t blp[2] = {bl[g][h * 2], bl[g][h * 2 + 1]};
                    mma_f16(d, af[mf], bhp);
                    mma_f16(d, af[mf], blp);
                }
            }
        }
        buf ^= 1;
    }

    const int lq = lane >> 2;
    const int lr = lane & 3;
#pragma unroll
    for (int mf = 0; mf < 2; mf++) {
#pragma unroll
        for (int g = 0; g < 2; g++) {
#pragma unroll
            for (int h = 0; h < 2; h++) {
                const float* d = acc[mf][g * 2 + h];
                const int col = colBase + warp_n * 32 + g * 16 + h * 8 + lr * 2;
                const int r0 = rowBase + warp_m * 32 + mf * 16 + lq;
                if (r0 < M)
                    *reinterpret_cast<__half2*>(C + (size_t)r0 * N + col) =
                        __floats2half2_rn(d[0], d[1]);
                const int r1 = r0 + 8;
                if (r1 < M)
                    *reinterpret_cast<__half2*>(C + (size_t)r1 * N + col) =
                        __floats2half2_rn(d[2], d[3]);
            }
        }
    }
}

// ---------------------------------------------------------------------------
// CSR aggregation from fp16 h — 32 threads/node, 8 dims (16B) per thread,
// 4-edge unroll. fp32 accumulate. RELU template toggles relu; fp16 output.
// ---------------------------------------------------------------------------
__device__ __forceinline__ void acc8_add(float* acc, const uint4& v, float cc) {
    const __half2* p = reinterpret_cast<const __half2*>(&v);
#pragma unroll
    for (int i = 0; i < 4; i++) {
        float2 f = __half22float2(p[i]);
        acc[2 * i + 0] = fmaf(cc, f.x, acc[2 * i + 0]);
        acc[2 * i + 1] = fmaf(cc, f.y, acc[2 * i + 1]);
    }
}

template <bool RELU>
__global__ __launch_bounds__(256)
void agg_csr_kernel(const __half* __restrict__ h, const float* __restrict__ bias,
                    const float* __restrict__ dinv,
                    const int* __restrict__ rowptr, const int* __restrict__ esrc,
                    const float* __restrict__ ecoef,
                    __half* __restrict__ outp, int n) {
    const int node = blockIdx.x * 8 + (threadIdx.x >> 5);
    if (node >= n) return;
    const int c = (threadIdx.x & 31) << 3;

    const float di = dinv[node];
    const float ws = di * di;
    float acc[8];
    {
        uint4 hv = *reinterpret_cast<const uint4*>(h + (size_t)node * DHID + c);
        const __half2* hh = reinterpret_cast<const __half2*>(&hv);
        float4 b0 = *reinterpret_cast<const float4*>(bias + c);
        float4 b1 = *reinterpret_cast<const float4*>(bias + c + 4);
        float2 f;
        f = __half22float2(hh[0]); acc[0] = fmaf(f.x, ws, b0.x); acc[1] = fmaf(f.y, ws, b0.y);
        f = __half22float2(hh[1]); acc[2] = fmaf(f.x, ws, b0.z); acc[3] = fmaf(f.y, ws, b0.w);
        f = __half22float2(hh[2]); acc[4] = fmaf(f.x, ws, b1.x); acc[5] = fmaf(f.y, ws, b1.y);
        f = __half22float2(hh[3]); acc[6] = fmaf(f.x, ws, b1.z); acc[7] = fmaf(f.y, ws, b1.w);
    }

    const int beg = rowptr[node];
    const int end = rowptr[node + 1];
    int e = beg;
    for (; e + 4 <= end; e += 4) {
        const int s0 = esrc[e + 0];
        const int s1 = esrc[e + 1];
        const int s2 = esrc[e + 2];
        const int s3 = esrc[e + 3];
        const float c0 = ecoef[e + 0];
        const float c1 = ecoef[e + 1];
        const float c2 = ecoef[e + 2];
        const float c3 = ecoef[e + 3];
        uint4 v0 = *reinterpret_cast<const uint4*>(h + (size_t)s0 * DHID + c);
        uint4 v1 = *reinterpret_cast<const uint4*>(h + (size_t)s1 * DHID + c);
        uint4 v2 = *reinterpret_cast<const uint4*>(h + (size_t)s2 * DHID + c);
        uint4 v3 = *reinterpret_cast<const uint4*>(h + (size_t)s3 * DHID + c);
        acc8_add(acc, v0, c0);
        acc8_add(acc, v1, c1);
        acc8_add(acc, v2, c2);
        acc8_add(acc, v3, c3);
    }
    for (; e < end; e++) {
        const int s0 = esrc[e];
        const float c0 = ecoef[e];
        uint4 v0 = *reinterpret_cast<const uint4*>(h + (size_t)s0 * DHID + c);
        acc8_add(acc, v0, c0);
    }

    if (RELU) {
#pragma unroll
        for (int i = 0; i < 8; i++) acc[i] = fmaxf(acc[i], 0.f);
    }
    uint4 o;
    __half2* op = reinterpret_cast<__half2*>(&o);
    op[0] = __floats2half2_rn(acc[0], acc[1]);
    op[1] = __floats2half2_rn(acc[2], acc[3]);
    op[2] = __floats2half2_rn(acc[4], acc[5]);
    op[3] = __floats2half2_rn(acc[6], acc[7]);
    *reinterpret_cast<uint4*>(outp + (size_t)node * DHID + c) = o;
}

// ---------------------------------------------------------------------------
// Edge scoring from fp16 features (one warp per edge, fp32 accumulate).
// ---------------------------------------------------------------------------
__global__ __launch_bounds__(256)
void score_fp16_kernel(const __half* __restrict__ h,
                       const int* __restrict__ src,
                       const int* __restrict__ dst,
                       float* __restrict__ out, int e) {
    unsigned gt = blockIdx.x * blockDim.x + threadIdx.x;
    unsigned ed = gt >> 5;
    const int lane = threadIdx.x & 31;
    if (ed >= (unsigned)e) return;
    const int s = src[ed];
    const int d = dst[ed];
    uint4 su = *(reinterpret_cast<const uint4*>(h + (size_t)s * DHID) + lane);
    uint4 du = *(reinterpret_cast<const uint4*>(h + (size_t)d * DHID) + lane);
    const __half2* sv = reinterpret_cast<const __half2*>(&su);
    const __half2* dv = reinterpret_cast<const __half2*>(&du);
    float acc = 0.0f;
#pragma unroll
    for (int i = 0; i < 4; i++) {
        float2 a = __half22float2(sv[i]);
        float2 b = __half22float2(dv[i]);
        acc = fmaf(a.x, b.x, acc);
        acc = fmaf(a.y, b.y, acc);
    }
#pragma unroll
    for (int off = 16; off > 0; off >>= 1)
        acc += __shfl_xor_sync(0xFFFFFFFFu, acc, off);
    if (lane == 0) out[ed] = 1.0f / (1.0f + expf(-acc));
}

// ---------------------------------------------------------------------------
// Host launcher — CSR build forked onto a side stream
// ---------------------------------------------------------------------------
extern "C" void kernel_launch(void* const* d_in, const int* in_sizes, int n_in,
                              void* d_out, int out_size) {
    const float* x  = (const float*)d_in[0];
    const int*   ei = (const int*)d_in[1];
    const float* W1 = (const float*)d_in[2];
    const float* b1 = (const float*)d_in[3];
    const float* W2 = (const float*)d_in[4];
    const float* b2 = (const float*)d_in[5];
    float* out = (float*)d_out;

    const int N = in_sizes[0] / DIN;
    const int E = in_sizes[1] / 2;
    const int* src = ei;
    const int* dst = ei + E;

    int *p_cnt, *p_rowptr, *p_off, *p_esrc, *p_bsum, *p_boff;
    float *p_dinv, *p_ecoef;
    __half *p_xf, *p_w1h, *p_w1l, *p_w2h, *p_w2l, *p_h1, *p_a1f, *p_h2, *p_agg2;
    cudaGetSymbolAddress((void**)&p_cnt,    g_cnt);
    cudaGetSymbolAddress((void**)&p_dinv,   g_dinv);
    cudaGetSymbolAddress((void**)&p_rowptr, g_rowptr);
    cudaGetSymbolAddress((void**)&p_off,    g_off);
    cudaGetSymbolAddress((void**)&p_bsum,   g_blocksum);
    cudaGetSymbolAddress((void**)&p_boff,   g_blockoff);
    cudaGetSymbolAddress((void**)&p_esrc,   g_esrc);
    cudaGetSymbolAddress((void**)&p_ecoef,  g_ecoef);
    cudaGetSymbolAddress((void**)&p_xf,     g_xf);
    cudaGetSymbolAddress((void**)&p_w1h,    g_w1h);
    cudaGetSymbolAddress((void**)&p_w1l,    g_w1l);
    cudaGetSymbolAddress((void**)&p_w2h,    g_w2h);
    cudaGetSymbolAddress((void**)&p_w2l,    g_w2l);
    cudaGetSymbolAddress((void**)&p_h1,     g_h1);
    cudaGetSymbolAddress((void**)&p_a1f,    g_a1f);
    cudaGetSymbolAddress((void**)&p_h2,     g_h2);
    cudaGetSymbolAddress((void**)&p_agg2,   g_agg2);

    static cudaStream_t s_side = nullptr;
    static cudaEvent_t  s_fork = nullptr, s_join = nullptr;
    if (s_side == nullptr) {
        cudaStreamCreateWithFlags(&s_side, cudaStreamNonBlocking);
        cudaEventCreateWithFlags(&s_fork, cudaEventDisableTiming);
        cudaEventCreateWithFlags(&s_join, cudaEventDisableTiming);
    }

    const int T = 256;

    // ---- fork: CSR build chain on side stream ----
    cudaEventRecord(s_fork, 0);
    cudaStreamWaitEvent(s_side, s_fork, 0);
    zero_cnt_kernel<<<(N + T - 1) / T, T, 0, s_side>>>(p_cnt, N);
    hist_kernel<<<(E + T - 1) / T, T, 0, s_side>>>(p_cnt, dst, E);
    dinv_kernel<<<(N + T - 1) / T, T, 0, s_side>>>(p_cnt, p_dinv, N);
    scan_p1_kernel<<<NB_SCAN, 256, 0, s_side>>>(p_cnt, p_bsum, N);
    scan_p2_kernel<<<1, NB_SCAN, 0, s_side>>>(p_bsum, p_boff, p_rowptr, N);
    scan_p3_kernel<<<NB_SCAN, 256, 0, s_side>>>(p_cnt, p_boff, p_rowptr, p_off, N);
    scatter_kernel<<<(E + T - 1) / T, T, 0, s_side>>>(src, dst, p_dinv, p_off,
                                                      p_esrc, p_ecoef, E);
    cudaEventRecord(s_join, s_side);

    // ---- main stream: converts/splits + GEMM1 ----
    {
        int n4 = N * DIN / 4;
        cvt16_kernel<<<(n4 + T - 1) / T, T>>>(x, p_xf, n4);
        int w1n4 = DIN * DHID / 4;
        split16_kernel<<<(w1n4 + T - 1) / T, T>>>(W1, p_w1h, p_w1l, w1n4);
        int w2n4 = DHID * DHID / 4;
        split16_kernel<<<(w2n4 + T - 1) / T, T>>>(W2, p_w2h, p_w2l, w2n4);
    }
    {
        dim3 grid(DHID / 64, (N + 127) / 128);
        mma_gemm_f16_kernel<<<grid, 256>>>(p_xf, p_w1h, p_w1l, p_h1, N, DIN, DHID);
    }

    // ---- join: agg1 needs CSR ----
    cudaStreamWaitEvent(0, s_join, 0);
    agg_csr_kernel<true><<<(N + 7) / 8, 256>>>(p_h1, b1, p_dinv, p_rowptr, p_esrc, p_ecoef,
                                               p_a1f, N);

    {
        dim3 grid(DHID / 64, (N + 127) / 128);
        mma_gemm_f16_kernel<<<grid, 256>>>(p_a1f, p_w2h, p_w2l, p_h2, N, DHID, DHID);
    }
    agg_csr_kernel<false><<<(N + 7) / 8, 256>>>(p_h2, b2, p_dinv, p_rowptr, p_esrc, p_ecoef,
                                                p_agg2, N);

    // ---- edge scoring from fp16 ----
    score_fp16_kernel<<<((unsigned)E * 32 + T - 1) / T, T>>>(p_agg2, src, dst, out, E);
}

// round 17
// speedup vs baseline: 1.4646x; 1.1002x over previous
#include <cuda_runtime.h>
#include <cuda_bf16.h>
#include <cuda_fp16.h>
#include <stdint.h>
#include <math.h>

#define MAX_N 50000
#define MAX_E 800000
#define DHID 256
#define DIN 512
#define NB_SCAN 128

// Scratch device globals
__device__ int   g_cnt[MAX_N];
__device__ float g_dinv[MAX_N];
__device__ int   g_rowptr[MAX_N + 1];
__device__ int   g_off[MAX_N];
__device__ int   g_blocksum[NB_SCAN];
__device__ int   g_blockoff[NB_SCAN];
__device__ int   g_esrc[MAX_E];
__device__ float g_ecoef[MAX_E];

__device__ __half g_xf[(size_t)MAX_N * DIN];     // x fp16
__device__ __half g_w1f[DIN * DHID];             // W1 fp16
__device__ __half g_w2f[DHID * DHID];            // W2 fp16
__device__ __half g_h1[(size_t)MAX_N * DHID];
__device__ __half g_a1f[(size_t)MAX_N * DHID];   // relu(agg1) fp16
__device__ __half g_h2[(size_t)MAX_N * DHID];
__device__ __half g_agg2[(size_t)MAX_N * DHID];

// ---------------------------------------------------------------------------
// CSR build
// ---------------------------------------------------------------------------
__global__ void zero_cnt_kernel(int* cnt, int n) {
    int i = blockIdx.x * blockDim.x + threadIdx.x;
    if (i < n) cnt[i] = 0;
}

__global__ void hist_kernel(int* cnt, const int* __restrict__ dst, int e) {
    int i = blockIdx.x * blockDim.x + threadIdx.x;
    if (i < e) atomicAdd(&cnt[dst[i]], 1);
}

__global__ void dinv_kernel(const int* __restrict__ cnt, float* __restrict__ dinv, int n) {
    int i = blockIdx.x * blockDim.x + threadIdx.x;
    if (i < n) dinv[i] = rsqrtf((float)(cnt[i] + 1));
}

__global__ __launch_bounds__(256)
void scan_p1_kernel(const int* __restrict__ cnt, int* __restrict__ blocksum, int n) {
    __shared__ int red[256];
    const int chunk = (n + NB_SCAN - 1) / NB_SCAN;
    const int beg = blockIdx.x * chunk;
    const int end = min(beg + chunk, n);
    int s = 0;
    for (int i = beg + threadIdx.x; i < end; i += 256) s += cnt[i];
    red[threadIdx.x] = s;
    __syncthreads();
    for (int d = 128; d > 0; d >>= 1) {
        if (threadIdx.x < d) red[threadIdx.x] += red[threadIdx.x + d];
        __syncthreads();
    }
    if (threadIdx.x == 0) blocksum[blockIdx.x] = red[0];
}

__global__ __launch_bounds__(NB_SCAN)
void scan_p2_kernel(const int* __restrict__ blocksum, int* __restrict__ blockoff,
                    int* __restrict__ rowptr, int n) {
    __shared__ int sh[NB_SCAN];
    const int t = threadIdx.x;
    sh[t] = blocksum[t];
    __syncthreads();
    for (int d = 1; d < NB_SCAN; d <<= 1) {
        int v = (t >= d) ? sh[t - d] : 0;
        __syncthreads();
        sh[t] += v;
        __syncthreads();
    }
    blockoff[t] = (t == 0) ? 0 : sh[t - 1];
    if (t == NB_SCAN - 1) rowptr[n] = sh[NB_SCAN - 1];
}

__global__ __launch_bounds__(256)
void scan_p3_kernel(const int* __restrict__ cnt, const int* __restrict__ blockoff,
                    int* __restrict__ rowptr, int* __restrict__ off, int n) {
    __shared__ int sh[256];
    const int chunk = (n + NB_SCAN - 1) / NB_SCAN;
    const int beg = blockIdx.x * chunk;
    const int end = min(beg + chunk, n);
    int running = blockoff[blockIdx.x];
    for (int base = beg; base < end; base += 256) {
        const int i = base + threadIdx.x;
        int v = (i < end) ? cnt[i] : 0;
        sh[threadIdx.x] = v;
        __syncthreads();
        for (int d = 1; d < 256; d <<= 1) {
            int t2 = (threadIdx.x >= d) ? sh[threadIdx.x - d] : 0;
            __syncthreads();
            sh[threadIdx.x] += t2;
            __syncthreads();
        }
        if (i < end) {
            const int excl = sh[threadIdx.x] - v;
            rowptr[i] = running + excl;
            off[i] = running + excl;
        }
        running += sh[255];
        __syncthreads();
    }
}

__global__ void scatter_kernel(const int* __restrict__ src, const int* __restrict__ dst,
                               const float* __restrict__ dinv, int* __restrict__ off,
                               int* __restrict__ esrc, float* __restrict__ ecoef, int e) {
    int i = blockIdx.x * blockDim.x + threadIdx.x;
    if (i < e) {
        const int s = src[i];
        const int d = dst[i];
        const int pos = atomicAdd(&off[d], 1);
        esrc[pos] = s;
        ecoef[pos] = dinv[s] * dinv[d];
    }
}

// ---------------------------------------------------------------------------
// fp32 -> fp16 convert
// ---------------------------------------------------------------------------
__global__ void cvt16_kernel(const float* __restrict__ in,
                             __half* __restrict__ outp, int n4) {
    int i = blockIdx.x * blockDim.x + threadIdx.x;
    if (i >= n4) return;
    float4 v = reinterpret_cast<const float4*>(in)[i];
    __half2 p0 = __floats2half2_rn(v.x, v.y);
    __half2 p1 = __floats2half2_rn(v.z, v.w);
    *reinterpret_cast<__half2*>(outp + i * 4) = p0;
    *reinterpret_cast<__half2*>(outp + i * 4 + 2) = p1;
}

// ---------------------------------------------------------------------------
// Tensor-core GEMM: C = A_fp16 @ B_fp16, fp32 accumulate, 1 MMA/step.
// CTA tile 128x64, BK=16, 8 warps (4m x 2n), warp tile 32x32, cp.async 2-stage.
// Epilogue writes fp16.
// ---------------------------------------------------------------------------
#define A_PAD 24
#define B_PAD 72

__device__ __forceinline__ void ldsm_x4(uint32_t addr, uint32_t& r0, uint32_t& r1,
                                        uint32_t& r2, uint32_t& r3) {
    asm volatile("ldmatrix.sync.aligned.m8n8.x4.shared.b16 {%0,%1,%2,%3}, [%4];"
                 : "=r"(r0), "=r"(r1), "=r"(r2), "=r"(r3) : "r"(addr));
}
__device__ __forceinline__ void ldsm_x4_t(uint32_t addr, uint32_t& r0, uint32_t& r1,
                                          uint32_t& r2, uint32_t& r3) {
    asm volatile("ldmatrix.sync.aligned.m8n8.x4.trans.shared.b16 {%0,%1,%2,%3}, [%4];"
                 : "=r"(r0), "=r"(r1), "=r"(r2), "=r"(r3) : "r"(addr));
}
__device__ __forceinline__ void mma_f16(float* d, const uint32_t* a, const uint32_t* b) {
    asm volatile("mma.sync.aligned.m16n8k16.row.col.f32.f16.f16.f32 "
                 "{%0,%1,%2,%3}, {%4,%5,%6,%7}, {%8,%9}, {%0,%1,%2,%3};"
                 : "+f"(d[0]), "+f"(d[1]), "+f"(d[2]), "+f"(d[3])
                 : "r"(a[0]), "r"(a[1]), "r"(a[2]), "r"(a[3]), "r"(b[0]), "r"(b[1]));
}
__device__ __forceinline__ void cp_async16(void* smem_dst, const void* gsrc, bool pred) {
    uint32_t saddr = (uint32_t)__cvta_generic_to_shared(smem_dst);
    int sz = pred ? 16 : 0;
    asm volatile("cp.async.cg.shared.global [%0], [%1], 16, %2;"
                 :: "r"(saddr), "l"(gsrc), "r"(sz));
}

__global__ __launch_bounds__(256)
void mma_gemm_f16_kernel(const __half* __restrict__ Ag,
                         const __half* __restrict__ Bg,
                         __half* __restrict__ C, int M, int K, int N) {
    __shared__ __half Af[2][128][A_PAD];
    __shared__ __half Bf[2][16][B_PAD];

    const int tid = threadIdx.x;
    const int wid = tid >> 5;
    const int lane = tid & 31;
    const int warp_m = wid & 3;
    const int warp_n = wid >> 2;
    const int rowBase = blockIdx.y * 128;
    const int colBase = blockIdx.x * 64;

    // A staging: 128 rows x 16 k fp16 = 256 chunks of 8 elems; 1 per thread
    const int a_r = tid >> 1;
    const int a_k = (tid & 1) << 3;
    const int arow = rowBase + a_r;
    const bool a_ok = (arow < M);
    // B staging: 16 rows x 64 cols = 128 chunks of 8; threads 0-127
    const int bt = tid & 127;
    const int b_r = bt >> 3;
    const int b_c = (bt & 7) << 3;
    const bool do_b = (tid < 128);

    const int lrow = lane & 7;
    const int lmat = lane >> 3;
    const int a_mloc = ((lmat & 1) << 3) + lrow;
    const int a_khalf = lmat >> 1;
    const int b_krow = ((lmat & 1) << 3) + lrow;
    const int b_nhalf = lmat >> 1;

    float acc[2][4][4];
#pragma unroll
    for (int i = 0; i < 2; i++)
#pragma unroll
        for (int j = 0; j < 4; j++)
#pragma unroll
            for (int q = 0; q < 4; q++) acc[i][j][q] = 0.0f;

    const int KT = K >> 4;

    {
        cp_async16(&Af[0][a_r][a_k], Ag + (size_t)arow * K + a_k, a_ok);
        if (do_b)
            cp_async16(&Bf[0][b_r][b_c], Bg + (size_t)b_r * N + colBase + b_c, true);
        asm volatile("cp.async.commit_group;");
    }

    int buf = 0;
    for (int kt = 0; kt < KT; kt++) {
        asm volatile("cp.async.wait_group 0;");
        __syncthreads();

        if (kt + 1 < KT) {
            const int k0 = (kt + 1) << 4;
            const int nb = buf ^ 1;
            cp_async16(&Af[nb][a_r][a_k], Ag + (size_t)arow * K + k0 + a_k, a_ok);
            if (do_b)
                cp_async16(&Bf[nb][b_r][b_c], Bg + (size_t)(k0 + b_r) * N + colBase + b_c, true);
            asm volatile("cp.async.commit_group;");
        }

        uint32_t af[2][4];
#pragma unroll
        for (int mf = 0; mf < 2; mf++) {
            const int m_base = warp_m * 32 + mf * 16;
            uint32_t addr = (uint32_t)__cvta_generic_to_shared(
                &Af[buf][m_base + a_mloc][a_khalf * 8]);
            ldsm_x4(addr, af[mf][0], af[mf][1], af[mf][2], af[mf][3]);
        }
        uint32_t bf[2][4];
#pragma unroll
        for (int g = 0; g < 2; g++) {
            const int n_base = warp_n * 32 + g * 16;
            uint32_t addr = (uint32_t)__cvta_generic_to_shared(
                &Bf[buf][b_krow][n_base + b_nhalf * 8]);
            ldsm_x4_t(addr, bf[g][0], bf[g][1], bf[g][2], bf[g][3]);
        }
#pragma unroll
        for (int mf = 0; mf < 2; mf++) {
#pragma unroll
            for (int g = 0; g < 2; g++) {
#pragma unroll
                for (int h = 0; h < 2; h++) {
                    float* d = acc[mf][g * 2 + h];
                    const uint32_t bp[2] = {bf[g][h * 2], bf[g][h * 2 + 1]};
                    mma_f16(d, af[mf], bp);
                }
            }
        }
        buf ^= 1;
    }

    const int lq = lane >> 2;
    const int lr = lane & 3;
#pragma unroll
    for (int mf = 0; mf < 2; mf++) {
#pragma unroll
        for (int g = 0; g < 2; g++) {
#pragma unroll
            for (int h = 0; h < 2; h++) {
                const float* d = acc[mf][g * 2 + h];
                const int col = colBase + warp_n * 32 + g * 16 + h * 8 + lr * 2;
                const int r0 = rowBase + warp_m * 32 + mf * 16 + lq;
                if (r0 < M)
                    *reinterpret_cast<__half2*>(C + (size_t)r0 * N + col) =
                        __floats2half2_rn(d[0], d[1]);
                const int r1 = r0 + 8;
                if (r1 < M)
                    *reinterpret_cast<__half2*>(C + (size_t)r1 * N + col) =
                        __floats2half2_rn(d[2], d[3]);
            }
        }
    }
}

// ---------------------------------------------------------------------------
// CSR aggregation from fp16 h — 32 threads/node, 8 dims (16B) per thread,
// 4-edge unroll. fp32 accumulate. RELU template toggles relu; fp16 output.
// ---------------------------------------------------------------------------
__device__ __forceinline__ void acc8_add(float* acc, const uint4& v, float cc) {
    const __half2* p = reinterpret_cast<const __half2*>(&v);
#pragma unroll
    for (int i = 0; i < 4; i++) {
        float2 f = __half22float2(p[i]);
        acc[2 * i + 0] = fmaf(cc, f.x, acc[2 * i + 0]);
        acc[2 * i + 1] = fmaf(cc, f.y, acc[2 * i + 1]);
    }
}

template <bool RELU>
__global__ __launch_bounds__(256)
void agg_csr_kernel(const __half* __restrict__ h, const float* __restrict__ bias,
                    const float* __restrict__ dinv,
                    const int* __restrict__ rowptr, const int* __restrict__ esrc,
                    const float* __restrict__ ecoef,
                    __half* __restrict__ outp, int n) {
    const int node = blockIdx.x * 8 + (threadIdx.x >> 5);
    if (node >= n) return;
    const int c = (threadIdx.x & 31) << 3;

    const float di = dinv[node];
    const float ws = di * di;
    float acc[8];
    {
        uint4 hv = *reinterpret_cast<const uint4*>(h + (size_t)node * DHID + c);
        const __half2* hh = reinterpret_cast<const __half2*>(&hv);
        float4 b0 = *reinterpret_cast<const float4*>(bias + c);
        float4 b1 = *reinterpret_cast<const float4*>(bias + c + 4);
        float2 f;
        f = __half22float2(hh[0]); acc[0] = fmaf(f.x, ws, b0.x); acc[1] = fmaf(f.y, ws, b0.y);
        f = __half22float2(hh[1]); acc[2] = fmaf(f.x, ws, b0.z); acc[3] = fmaf(f.y, ws, b0.w);
        f = __half22float2(hh[2]); acc[4] = fmaf(f.x, ws, b1.x); acc[5] = fmaf(f.y, ws, b1.y);
        f = __half22float2(hh[3]); acc[6] = fmaf(f.x, ws, b1.z); acc[7] = fmaf(f.y, ws, b1.w);
    }

    const int beg = rowptr[node];
    const int end = rowptr[node + 1];
    int e = beg;
    for (; e + 4 <= end; e += 4) {
        const int s0 = esrc[e + 0];
        const int s1 = esrc[e + 1];
        const int s2 = esrc[e + 2];
        const int s3 = esrc[e + 3];
        const float c0 = ecoef[e + 0];
        const float c1 = ecoef[e + 1];
        const float c2 = ecoef[e + 2];
        const float c3 = ecoef[e + 3];
        uint4 v0 = *reinterpret_cast<const uint4*>(h + (size_t)s0 * DHID + c);
        uint4 v1 = *reinterpret_cast<const uint4*>(h + (size_t)s1 * DHID + c);
        uint4 v2 = *reinterpret_cast<const uint4*>(h + (size_t)s2 * DHID + c);
        uint4 v3 = *reinterpret_cast<const uint4*>(h + (size_t)s3 * DHID + c);
        acc8_add(acc, v0, c0);
        acc8_add(acc, v1, c1);
        acc8_add(acc, v2, c2);
        acc8_add(acc, v3, c3);
    }
    for (; e < end; e++) {
        const int s0 = esrc[e];
        const float c0 = ecoef[e];
        uint4 v0 = *reinterpret_cast<const uint4*>(h + (size_t)s0 * DHID + c);
        acc8_add(acc, v0, c0);
    }

    if (RELU) {
#pragma unroll
        for (int i = 0; i < 8; i++) acc[i] = fmaxf(acc[i], 0.f);
    }
    uint4 o;
    __half2* op = reinterpret_cast<__half2*>(&o);
    op[0] = __floats2half2_rn(acc[0], acc[1]);
    op[1] = __floats2half2_rn(acc[2], acc[3]);
    op[2] = __floats2half2_rn(acc[4], acc[5]);
    op[3] = __floats2half2_rn(acc[6], acc[7]);
    *reinterpret_cast<uint4*>(outp + (size_t)node * DHID + c) = o;
}

// ---------------------------------------------------------------------------
// Edge scoring from fp16 features (one warp per edge, fp32 accumulate).
// ---------------------------------------------------------------------------
__global__ __launch_bounds__(256)
void score_fp16_kernel(const __half* __restrict__ h,
                       const int* __restrict__ src,
                       const int* __restrict__ dst,
                       float* __restrict__ out, int e) {
    unsigned gt = blockIdx.x * blockDim.x + threadIdx.x;
    unsigned ed = gt >> 5;
    const int lane = threadIdx.x & 31;
    if (ed >= (unsigned)e) return;
    const int s = src[ed];
    const int d = dst[ed];
    uint4 su = *(reinterpret_cast<const uint4*>(h + (size_t)s * DHID) + lane);
    uint4 du = *(reinterpret_cast<const uint4*>(h + (size_t)d * DHID) + lane);
    const __half2* sv = reinterpret_cast<const __half2*>(&su);
    const __half2* dv = reinterpret_cast<const __half2*>(&du);
    float acc = 0.0f;
#pragma unroll
    for (int i = 0; i < 4; i++) {
        float2 a = __half22float2(sv[i]);
        float2 b = __half22float2(dv[i]);
        acc = fmaf(a.x, b.x, acc);
        acc = fmaf(a.y, b.y, acc);
    }
#pragma unroll
    for (int off = 16; off > 0; off >>= 1)
        acc += __shfl_xor_sync(0xFFFFFFFFu, acc, off);
    if (lane == 0) out[ed] = 1.0f / (1.0f + expf(-acc));
}

// ---------------------------------------------------------------------------
// Host launcher — CSR build forked onto a side stream
// ---------------------------------------------------------------------------
extern "C" void kernel_launch(void* const* d_in, const int* in_sizes, int n_in,
                              void* d_out, int out_size) {
    const float* x  = (const float*)d_in[0];
    const int*   ei = (const int*)d_in[1];
    const float* W1 = (const float*)d_in[2];
    const float* b1 = (const float*)d_in[3];
    const float* W2 = (const float*)d_in[4];
    const float* b2 = (const float*)d_in[5];
    float* out = (float*)d_out;

    const int N = in_sizes[0] / DIN;
    const int E = in_sizes[1] / 2;
    const int* src = ei;
    const int* dst = ei + E;

    int *p_cnt, *p_rowptr, *p_off, *p_esrc, *p_bsum, *p_boff;
    float *p_dinv, *p_ecoef;
    __half *p_xf, *p_w1f, *p_w2f, *p_h1, *p_a1f, *p_h2, *p_agg2;
    cudaGetSymbolAddress((void**)&p_cnt,    g_cnt);
    cudaGetSymbolAddress((void**)&p_dinv,   g_dinv);
    cudaGetSymbolAddress((void**)&p_rowptr, g_rowptr);
    cudaGetSymbolAddress((void**)&p_off,    g_off);
    cudaGetSymbolAddress((void**)&p_bsum,   g_blocksum);
    cudaGetSymbolAddress((void**)&p_boff,   g_blockoff);
    cudaGetSymbolAddress((void**)&p_esrc,   g_esrc);
    cudaGetSymbolAddress((void**)&p_ecoef,  g_ecoef);
    cudaGetSymbolAddress((void**)&p_xf,     g_xf);
    cudaGetSymbolAddress((void**)&p_w1f,    g_w1f);
    cudaGetSymbolAddress((void**)&p_w2f,    g_w2f);
    cudaGetSymbolAddress((void**)&p_h1,     g_h1);
    cudaGetSymbolAddress((void**)&p_a1f,    g_a1f);
    cudaGetSymbolAddress((void**)&p_h2,     g_h2);
    cudaGetSymbolAddress((void**)&p_agg2,   g_agg2);

    static cudaStream_t s_side = nullptr;
    static cudaEvent_t  s_fork = nullptr, s_join = nullptr;
    if (s_side == nullptr) {
        cudaStreamCreateWithFlags(&s_side, cudaStreamNonBlocking);
        cudaEventCreateWithFlags(&s_fork, cudaEventDisableTiming);
        cudaEventCreateWithFlags(&s_join, cudaEventDisableTiming);
    }

    const int T = 256;

    // ---- fork: CSR build chain on side stream ----
    cudaEventRecord(s_fork, 0);
    cudaStreamWaitEvent(s_side, s_fork, 0);
    zero_cnt_kernel<<<(N + T - 1) / T, T, 0, s_side>>>(p_cnt, N);
    hist_kernel<<<(E + T - 1) / T, T, 0, s_side>>>(p_cnt, dst, E);
    dinv_kernel<<<(N + T - 1) / T, T, 0, s_side>>>(p_cnt, p_dinv, N);
    scan_p1_kernel<<<NB_SCAN, 256, 0, s_side>>>(p_cnt, p_bsum, N);
    scan_p2_kernel<<<1, NB_SCAN, 0, s_side>>>(p_bsum, p_boff, p_rowptr, N);
    scan_p3_kernel<<<NB_SCAN, 256, 0, s_side>>>(p_cnt, p_boff, p_rowptr, p_off, N);
    scatter_kernel<<<(E + T - 1) / T, T, 0, s_side>>>(src, dst, p_dinv, p_off,
                                                      p_esrc, p_ecoef, E);
    cudaEventRecord(s_join, s_side);

    // ---- main stream: converts + GEMM1 ----
    {
        int n4 = N * DIN / 4;
        cvt16_kernel<<<(n4 + T - 1) / T, T>>>(x, p_xf, n4);
        int w1n4 = DIN * DHID / 4;
        cvt16_kernel<<<(w1n4 + T - 1) / T, T>>>(W1, p_w1f, w1n4);
        int w2n4 = DHID * DHID / 4;
        cvt16_kernel<<<(w2n4 + T - 1) / T, T>>>(W2, p_w2f, w2n4);
    }
    {
        dim3 grid(DHID / 64, (N + 127) / 128);
        mma_gemm_f16_kernel<<<grid, 256>>>(p_xf, p_w1f, p_h1, N, DIN, DHID);
    }

    // ---- join: agg1 needs CSR ----
    cudaStreamWaitEvent(0, s_join, 0);
    agg_csr_kernel<true><<<(N + 7) / 8, 256>>>(p_h1, b1, p_dinv, p_rowptr, p_esrc, p_ecoef,
                                               p_a1f, N);

    {
        dim3 grid(DHID / 64, (N + 127) / 128);
        mma_gemm_f16_kernel<<<grid, 256>>>(p_a1f, p_w2f, p_h2, N, DHID, DHID);
    }
    agg_csr_kernel<false><<<(N + 7) / 8, 256>>>(p_h2, b2, p_dinv, p_rowptr, p_esrc, p_ecoef,
                                                p_agg2, N);

    // ---- edge scoring from fp16 ----
    score_fp16_kernel<<<((unsigned)E * 32 + T - 1) / T, T>>>(p_agg2, src, dst, out, E);
}